// round 11
// baseline (speedup 1.0000x reference)
#include <cuda_runtime.h>
#include <cuda_bf16.h>
#include <math.h>
#include <stdint.h>

#define B_  4
#define T_  2048
#define E_  1024
#define H_  16
#define DH_ 64
#define NL_ 4
#define FF_ 4096
#define V_  32000
#define BT_ (B_*T_)        // 8192 tokens
#define MQKV_ (BT_*H_)     // 131072 per-head rows

// ---------------- scratch (static device allocations; no cudaMalloc) -------
__device__ float g_x[BT_*E_];
__device__ float g_y[BT_*E_];
__device__ float g_qkv[(size_t)MQKV_*256];   // packed q|k|v|pad, row stride 256
__device__ float g_att[BT_*E_];
__device__ float g_h[(size_t)BT_*FF_];
__device__ float g_logits[(size_t)BT_*V_];
__device__ float g_tokloss[BT_];
// bf16 hi/lo split buffers
__device__ __nv_bfloat16 g_ah[(size_t)BT_*FF_];
__device__ __nv_bfloat16 g_al[(size_t)BT_*FF_];
__device__ __nv_bfloat16 g_wh[(size_t)V_*E_];
__device__ __nv_bfloat16 g_wl[(size_t)V_*E_];
__device__ __nv_bfloat16 g_wqh[256*64];
__device__ __nv_bfloat16 g_wql[256*64];

// ======================= low-level helpers =================================
__device__ __forceinline__ uint32_t smem_u32(const void* p) {
    uint32_t a;
    asm("{ .reg .u64 t; cvta.to.shared.u64 t, %1; cvt.u32.u64 %0, t; }"
        : "=r"(a) : "l"(p));
    return a;
}
__device__ __forceinline__ void cp16(uint32_t dst, const void* src) {
    asm volatile("cp.async.cg.shared.global [%0], [%1], 16;\n"
                 :: "r"(dst), "l"(src));
}
__device__ __forceinline__ void cp_commit() {
    asm volatile("cp.async.commit_group;" ::: "memory");
}
__device__ __forceinline__ void cp_wait1() {
    asm volatile("cp.async.wait_group 1;" ::: "memory");
}
__device__ __forceinline__ void cp_wait0() {
    asm volatile("cp.async.wait_group 0;" ::: "memory");
}
#define LDSM4(r0,r1,r2,r3,addr) \
    asm volatile("ldmatrix.sync.aligned.m8n8.x4.shared.b16 {%0,%1,%2,%3}, [%4];" \
        : "=r"(r0),"=r"(r1),"=r"(r2),"=r"(r3) : "r"(addr))
#define LDSM2(r0,r1,addr) \
    asm volatile("ldmatrix.sync.aligned.m8n8.x2.shared.b16 {%0,%1}, [%2];" \
        : "=r"(r0),"=r"(r1) : "r"(addr))
#define MMA16816(c,a,b) \
    asm volatile("mma.sync.aligned.m16n8k16.row.col.f32.bf16.bf16.f32 " \
        "{%0,%1,%2,%3}, {%4,%5,%6,%7}, {%8,%9}, {%0,%1,%2,%3};" \
        : "+f"((c)[0]),"+f"((c)[1]),"+f"((c)[2]),"+f"((c)[3]) \
        : "r"((a)[0]),"r"((a)[1]),"r"((a)[2]),"r"((a)[3]), \
          "r"((b)[0]),"r"((b)[1]))

// ======================= bf16 hi/lo HMMA GEMM ==============================
// C[M,N] = (Ah+Al)[M,K] @ (Bh+Bl)[N,K]^T, fp32 out, 3-pass split precision.
// Block 128x128, K-chunk 32, 16 warps (4M x 4N, warp tile 32x32), 2-stage
// cp.async pipeline, 80B-padded smem rows (conflict-free ldmatrix).
// ~95 regs/thread -> 512 threads resident (16 warps/SM, 4/SMSP).
#define EPI_BIAS 1
#define EPI_RES  2
#define EPI_GELU 4

#define PAD_ROW 80                    // bytes per smem row: 64B data + 16B pad
#define TILE_BYTES (128*PAD_ROW)      // 10240
#define S_AH 0
#define S_AL (TILE_BYTES)
#define S_BH (2*TILE_BYTES)
#define S_BL (3*TILE_BYTES)
#define STAGE_MM (4*TILE_BYTES)       // 40960
#define SMEM_MM  (2*STAGE_MM)         // 81920

__device__ __forceinline__ void mm_load(
    uint32_t st, const __nv_bfloat16* __restrict__ Ah,
    const __nv_bfloat16* __restrict__ Al,
    const __nv_bfloat16* __restrict__ Bh,
    const __nv_bfloat16* __restrict__ Bl,
    int m0, int n0, int K, int k0, int tid)
{
    const int row = tid >> 2;            // 0..127
    const int c16 = tid & 3;
    const uint32_t so = row * PAD_ROW + c16 * 16;
    const size_t goA = (size_t)(m0 + row) * K + k0 + c16 * 8;
    const size_t goB = (size_t)(n0 + row) * K + k0 + c16 * 8;
    cp16(st + S_AH + so, Ah + goA);
    cp16(st + S_AL + so, Al + goA);
    cp16(st + S_BH + so, Bh + goB);
    cp16(st + S_BL + so, Bl + goB);
}

template<int EPI>
__global__ void __launch_bounds__(512) gemm_mm(
    const __nv_bfloat16* __restrict__ Ah, const __nv_bfloat16* __restrict__ Al,
    const __nv_bfloat16* __restrict__ Bh, const __nv_bfloat16* __restrict__ Bl,
    const float* __restrict__ bias, const float* __restrict__ res,
    float* __restrict__ C, int M, int N, int K)
{
    extern __shared__ char smraw[];
    const uint32_t sb = smem_u32(smraw);
    const int tid  = threadIdx.x;
    const int lane = tid & 31;
    const int wid  = tid >> 5;            // 0..15
    const int wm = (wid & 3) * 32;        // warp M offset in block
    const int wn = (wid >> 2) * 32;       // warp N offset in block
    const int m0 = blockIdx.x * 128;
    const int n0 = blockIdx.y * 128;
    const int NC = K >> 5;                // chunks of 32

    float c[2][4][4];
    #pragma unroll
    for (int i = 0; i < 2; i++)
        #pragma unroll
        for (int j = 0; j < 4; j++)
            #pragma unroll
            for (int r = 0; r < 4; r++) c[i][j][r] = 0.f;

    // ldmatrix per-lane address components (constant across chunks)
    const int a_row = wm + (lane & 15);            // mi adds 16
    const int a_kof = (lane >> 4) * 8;
    const int b_row = wn + (lane & 7);             // ni adds 8
    const int b_kof = ((lane >> 3) & 1) * 8;

    mm_load(sb, Ah, Al, Bh, Bl, m0, n0, K, 0, tid);
    cp_commit();

    for (int ck = 0; ck < NC; ck++) {
        if (ck + 1 < NC) {
            mm_load(sb + ((ck + 1) & 1) * STAGE_MM, Ah, Al, Bh, Bl,
                    m0, n0, K, (ck + 1) << 5, tid);
            cp_commit();
            cp_wait1();
        } else {
            cp_wait0();
        }
        __syncthreads();

        const uint32_t st = sb + (ck & 1) * STAGE_MM;
        #pragma unroll
        for (int ks = 0; ks < 2; ks++) {
            const int k0 = ks * 16;
            uint32_t ah[2][4], al[2][4], bh[4][2], bl[4][2];
            #pragma unroll
            for (int mi = 0; mi < 2; mi++) {
                uint32_t ad = st + (a_row + mi * 16) * PAD_ROW + (k0 + a_kof) * 2;
                LDSM4(ah[mi][0], ah[mi][1], ah[mi][2], ah[mi][3], ad + S_AH);
                LDSM4(al[mi][0], al[mi][1], al[mi][2], al[mi][3], ad + S_AL);
            }
            #pragma unroll
            for (int ni = 0; ni < 4; ni++) {
                uint32_t bd = st + (b_row + ni * 8) * PAD_ROW + (k0 + b_kof) * 2;
                LDSM2(bh[ni][0], bh[ni][1], bd + S_BH);
                LDSM2(bl[ni][0], bl[ni][1], bd + S_BL);
            }
            // pass 1: Ah*Bh — swept over all 8 fragments (RAW distance = 8)
            #pragma unroll
            for (int mi = 0; mi < 2; mi++)
                #pragma unroll
                for (int ni = 0; ni < 4; ni++)
                    MMA16816(c[mi][ni], ah[mi], bh[ni]);
            // pass 2: Ah*Bl
            #pragma unroll
            for (int mi = 0; mi < 2; mi++)
                #pragma unroll
                for (int ni = 0; ni < 4; ni++)
                    MMA16816(c[mi][ni], ah[mi], bl[ni]);
            // pass 3: Al*Bh
            #pragma unroll
            for (int mi = 0; mi < 2; mi++)
                #pragma unroll
                for (int ni = 0; ni < 4; ni++)
                    MMA16816(c[mi][ni], al[mi], bh[ni]);
        }
        __syncthreads();
    }

    // epilogue: c frag rows = lane>>2 (+8), cols = 2*(lane&3) (+1)
    #pragma unroll
    for (int mi = 0; mi < 2; mi++) {
        const int mr = m0 + wm + mi * 16 + (lane >> 2);
        #pragma unroll
        for (int half = 0; half < 2; half++) {
            const int m = mr + half * 8;
            #pragma unroll
            for (int ni = 0; ni < 4; ni++) {
                const int n = n0 + wn + ni * 8 + 2 * (lane & 3);
                float v0 = c[mi][ni][half * 2 + 0];
                float v1 = c[mi][ni][half * 2 + 1];
                if (EPI & EPI_BIAS) { v0 += bias[n]; v1 += bias[n + 1]; }
                if (EPI & EPI_RES) {
                    float2 r2 = *(const float2*)(res + (size_t)m * N + n);
                    v0 += r2.x; v1 += r2.y;
                }
                if (EPI & EPI_GELU) {
                    v0 = 0.5f * v0 * (1.f + erff(v0 * 0.70710678118654752f));
                    v1 = 0.5f * v1 * (1.f + erff(v1 * 0.70710678118654752f));
                }
                *(float2*)(C + (size_t)m * N + n) = make_float2(v0, v1);
            }
        }
    }
}

// ---------------- fp32 -> bf16 hi/lo conversion ----------------------------
__global__ void __launch_bounds__(256) cvt_kernel(
    const float* __restrict__ in, __nv_bfloat16* __restrict__ hi,
    __nv_bfloat16* __restrict__ lo, int n4)
{
    int i = blockIdx.x * 256 + threadIdx.x;
    if (i >= n4) return;
    float4 x = ((const float4*)in)[i];
    __nv_bfloat16 h0 = __float2bfloat16(x.x);
    __nv_bfloat16 h1 = __float2bfloat16(x.y);
    __nv_bfloat16 h2 = __float2bfloat16(x.z);
    __nv_bfloat16 h3 = __float2bfloat16(x.w);
    __nv_bfloat16 l0 = __float2bfloat16(x.x - __bfloat162float(h0));
    __nv_bfloat16 l1 = __float2bfloat16(x.y - __bfloat162float(h1));
    __nv_bfloat16 l2 = __float2bfloat16(x.z - __bfloat162float(h2));
    __nv_bfloat16 l3 = __float2bfloat16(x.w - __bfloat162float(h3));
    ((__nv_bfloat162*)hi)[2*i]   = __nv_bfloat162(h0, h1);
    ((__nv_bfloat162*)hi)[2*i+1] = __nv_bfloat162(h2, h3);
    ((__nv_bfloat162*)lo)[2*i]   = __nv_bfloat162(l0, l1);
    ((__nv_bfloat162*)lo)[2*i+1] = __nv_bfloat162(l2, l3);
}

// ---------------- pack Wq|Wk|Wv -> padded [256 x 64] bf16 hi/lo ------------
__global__ void __launch_bounds__(256) pack_qkv_kernel(
    const float* __restrict__ Wq, const float* __restrict__ Wk,
    const float* __restrict__ Wv,
    __nv_bfloat16* __restrict__ wh, __nv_bfloat16* __restrict__ wl)
{
    int i = blockIdx.x * 256 + threadIdx.x;   // 0..16383
    int row = i >> 6, col = i & 63;
    float v = 0.f;
    if (row < 64)       v = Wq[row * 64 + col];
    else if (row < 128) v = Wk[(row - 64) * 64 + col];
    else if (row < 192) v = Wv[(row - 128) * 64 + col];
    __nv_bfloat16 h = __float2bfloat16(v);
    wh[i] = h;
    wl[i] = __float2bfloat16(v - __bfloat162float(h));
}

// ---------------- flash attention (causal, online softmax, fp32) -----------
// reads packed qkv rows of stride 256: [q(64) | k(64) | v(64) | pad(64)]
#define ATTN_SMEM_FLOATS (4*64*65 + 3*64)
#define ATTN_SMEM_BYTES  (ATTN_SMEM_FLOATS * 4)

__global__ void __launch_bounds__(256) attn_kernel(
    const float* __restrict__ qkv, float* __restrict__ out)
{
    extern __shared__ float sm[];
    float* Qs  = sm;
    float* Ks  = sm + 64*65;
    float* Vs  = sm + 2*64*65;
    float* Ps  = sm + 3*64*65;
    float* m_s = sm + 4*64*65;
    float* l_s = m_s + 64;
    float* al_s= l_s + 64;

    const int qt = blockIdx.x;
    const int bh = blockIdx.y;
    const int b  = bh / H_, h = bh % H_;
    const int q0 = qt * 64;
    const int tid = threadIdx.x;
    const int tx = tid & 15, ty = tid >> 4;

    {
        int r  = tid >> 2;
        int c0 = (tid & 3) * 16;
        const float* src = qkv + ((size_t)(b * T_ + q0 + r) * H_ + h) * 256 + c0;
        #pragma unroll
        for (int j = 0; j < 4; j++) {
            float4 t4 = *(const float4*)(src + j*4);
            Qs[r*65 + c0 + j*4 + 0] = t4.x;
            Qs[r*65 + c0 + j*4 + 1] = t4.y;
            Qs[r*65 + c0 + j*4 + 2] = t4.z;
            Qs[r*65 + c0 + j*4 + 3] = t4.w;
        }
    }
    if (tid < 64) { m_s[tid] = -1e30f; l_s[tid] = 0.f; }

    float o[4][4];
    #pragma unroll
    for (int i = 0; i < 4; i++)
        #pragma unroll
        for (int j = 0; j < 4; j++) o[i][j] = 0.f;

    for (int kt = 0; kt <= qt; kt++) {
        const int k0 = kt * 64;
        __syncthreads();
        {
            int r  = tid >> 2;
            int c0 = (tid & 3) * 16;
            const float* base = qkv + ((size_t)(b * T_ + k0 + r) * H_ + h) * 256;
            #pragma unroll
            for (int j = 0; j < 4; j++) {
                float4 t4 = *(const float4*)(base + 64 + c0 + j*4);
                Ks[r*65+c0+j*4+0] = t4.x; Ks[r*65+c0+j*4+1] = t4.y;
                Ks[r*65+c0+j*4+2] = t4.z; Ks[r*65+c0+j*4+3] = t4.w;
                float4 u4 = *(const float4*)(base + 128 + c0 + j*4);
                Vs[r*65+c0+j*4+0] = u4.x; Vs[r*65+c0+j*4+1] = u4.y;
                Vs[r*65+c0+j*4+2] = u4.z; Vs[r*65+c0+j*4+3] = u4.w;
            }
        }
        __syncthreads();

        float s[4][4];
        #pragma unroll
        for (int i = 0; i < 4; i++)
            #pragma unroll
            for (int j = 0; j < 4; j++) s[i][j] = 0.f;
        for (int d = 0; d < 64; d++) {
            float a[4], bb[4];
            #pragma unroll
            for (int i = 0; i < 4; i++) a[i]  = Qs[(ty*4+i)*65 + d];
            #pragma unroll
            for (int j = 0; j < 4; j++) bb[j] = Ks[(tx*4+j)*65 + d];
            #pragma unroll
            for (int i = 0; i < 4; i++)
                #pragma unroll
                for (int j = 0; j < 4; j++)
                    s[i][j] = fmaf(a[i], bb[j], s[i][j]);
        }
        const bool diag = (kt == qt);
        #pragma unroll
        for (int i = 0; i < 4; i++)
            #pragma unroll
            for (int j = 0; j < 4; j++) {
                float val = s[i][j] * 0.125f;
                if (diag && (tx*4+j) > (ty*4+i)) val = -1e30f;
                Ps[(ty*4+i)*65 + tx*4+j] = val;
            }
        __syncthreads();

        {
            int r  = tid >> 2;
            int c0 = (tid & 3) * 16;
            float mx = -1e30f;
            for (int c = 0; c < 16; c++) mx = fmaxf(mx, Ps[r*65 + c0 + c]);
            mx = fmaxf(mx, __shfl_xor_sync(0xffffffffu, mx, 1));
            mx = fmaxf(mx, __shfl_xor_sync(0xffffffffu, mx, 2));
            float m_old = m_s[r];
            float m_new = fmaxf(m_old, mx);
            float ssum = 0.f;
            for (int c = 0; c < 16; c++) {
                float p = __expf(Ps[r*65 + c0 + c] - m_new);
                Ps[r*65 + c0 + c] = p;
                ssum += p;
            }
            ssum += __shfl_xor_sync(0xffffffffu, ssum, 1);
            ssum += __shfl_xor_sync(0xffffffffu, ssum, 2);
            if ((tid & 3) == 0) {
                float alpha = __expf(m_old - m_new);
                al_s[r] = alpha;
                m_s[r]  = m_new;
                l_s[r]  = l_s[r] * alpha + ssum;
            }
        }
        __syncthreads();

        float al[4];
        #pragma unroll
        for (int i = 0; i < 4; i++) al[i] = al_s[ty*4+i];
        #pragma unroll
        for (int i = 0; i < 4; i++)
            #pragma unroll
            for (int j = 0; j < 4; j++) o[i][j] *= al[i];
        for (int c = 0; c < 64; c++) {
            float p[4], vv[4];
            #pragma unroll
            for (int i = 0; i < 4; i++) p[i]  = Ps[(ty*4+i)*65 + c];
            #pragma unroll
            for (int j = 0; j < 4; j++) vv[j] = Vs[c*65 + tx*4+j];
            #pragma unroll
            for (int i = 0; i < 4; i++)
                #pragma unroll
                for (int j = 0; j < 4; j++)
                    o[i][j] = fmaf(p[i], vv[j], o[i][j]);
        }
    }

    #pragma unroll
    for (int i = 0; i < 4; i++) {
        int r = ty*4 + i;
        float inv = 1.0f / l_s[r];
        float* dst = out + ((size_t)(b * T_ + q0 + r) * H_ + h) * DH_ + tx*4;
        #pragma unroll
        for (int j = 0; j < 4; j++) dst[j] = o[i][j] * inv;
    }
}

// ---------------- layernorm ------------------------------------------------
__global__ void __launch_bounds__(256) ln_kernel(
    const float* __restrict__ in, const float* __restrict__ gg,
    const float* __restrict__ bb, float* __restrict__ out)
{
    __shared__ float red[8];
    const int row = blockIdx.x;
    const int tid = threadIdx.x;
    float4 vx = ((const float4*)(in + (size_t)row * E_))[tid];
    float s = vx.x + vx.y + vx.z + vx.w;
    #pragma unroll
    for (int o = 16; o; o >>= 1) s += __shfl_xor_sync(0xffffffffu, s, o);
    if ((tid & 31) == 0) red[tid >> 5] = s;
    __syncthreads();
    float mean = (red[0]+red[1]+red[2]+red[3]+red[4]+red[5]+red[6]+red[7]) * (1.f/E_);
    __syncthreads();
    float dx = vx.x - mean, dy = vx.y - mean, dz = vx.z - mean, dw = vx.w - mean;
    float s2 = dx*dx + dy*dy + dz*dz + dw*dw;
    #pragma unroll
    for (int o = 16; o; o >>= 1) s2 += __shfl_xor_sync(0xffffffffu, s2, o);
    if ((tid & 31) == 0) red[tid >> 5] = s2;
    __syncthreads();
    float var = (red[0]+red[1]+red[2]+red[3]+red[4]+red[5]+red[6]+red[7]) * (1.f/E_);
    float rstd = rsqrtf(var + 1e-5f);
    float4 g4 = ((const float4*)gg)[tid];
    float4 b4 = ((const float4*)bb)[tid];
    float4 o4 = make_float4(dx*rstd*g4.x + b4.x, dy*rstd*g4.y + b4.y,
                            dz*rstd*g4.z + b4.z, dw*rstd*g4.w + b4.w);
    ((float4*)(out + (size_t)row * E_))[tid] = o4;
}

// ---------------- token+pos embedding --------------------------------------
__global__ void __launch_bounds__(256) embed_kernel(
    const int* __restrict__ idx, const float* __restrict__ tok,
    const float* __restrict__ pos, float* __restrict__ out)
{
    int gid = blockIdx.x * 256 + threadIdx.x;
    int e4 = gid & (E_/4 - 1);
    int bt = gid >> 8;
    int t  = bt & (T_ - 1);
    int token = idx[bt];
    float4 a = ((const float4*)(tok + (size_t)token * E_))[e4];
    float4 p = ((const float4*)(pos + (size_t)t * E_))[e4];
    ((float4*)out)[gid] = make_float4(a.x+p.x, a.y+p.y, a.z+p.z, a.w+p.w);
}

// ---------------- loss -----------------------------------------------------
__global__ void __launch_bounds__(256) loss_tok_kernel(
    const float* __restrict__ logits, const int* __restrict__ targets,
    float* __restrict__ tokloss)
{
    __shared__ float red[8];
    const int row = blockIdx.x;
    const int tid = threadIdx.x;
    const float* lg = logits + (size_t)row * V_;
    float mx = -1e30f;
    for (int i = tid; i < V_; i += 256) mx = fmaxf(mx, lg[i]);
    #pragma unroll
    for (int o = 16; o; o >>= 1) mx = fmaxf(mx, __shfl_xor_sync(0xffffffffu, mx, o));
    if ((tid & 31) == 0) red[tid >> 5] = mx;
    __syncthreads();
    mx = fmaxf(fmaxf(fmaxf(red[0], red[1]), fmaxf(red[2], red[3])),
               fmaxf(fmaxf(red[4], red[5]), fmaxf(red[6], red[7])));
    __syncthreads();
    float s = 0.f;
    for (int i = tid; i < V_; i += 256) s += __expf(lg[i] - mx);
    #pragma unroll
    for (int o = 16; o; o >>= 1) s += __shfl_xor_sync(0xffffffffu, s, o);
    if ((tid & 31) == 0) red[tid >> 5] = s;
    __syncthreads();
    if (tid == 0) {
        float tot = red[0]+red[1]+red[2]+red[3]+red[4]+red[5]+red[6]+red[7];
        tokloss[row] = -(lg[targets[row]] - mx - logf(tot));
    }
}

__global__ void __launch_bounds__(256) loss_reduce_kernel(
    const float* __restrict__ tokloss, float* __restrict__ outp)
{
    __shared__ float red[8];
    const int tid = threadIdx.x;
    float s = 0.f;
    for (int i = tid; i < BT_; i += 256) s += tokloss[i];
    #pragma unroll
    for (int o = 16; o; o >>= 1) s += __shfl_xor_sync(0xffffffffu, s, o);
    if ((tid & 31) == 0) red[tid >> 5] = s;
    __syncthreads();
    if (tid == 0) {
        float tot = red[0]+red[1]+red[2]+red[3]+red[4]+red[5]+red[6]+red[7];
        outp[0] = tot / (float)BT_;
    }
}

// ---------------- host driver ----------------------------------------------
extern "C" void kernel_launch(void* const* d_in, const int* in_sizes, int n_in,
                              void* d_out, int out_size)
{
    const int*   idx  = (const int*)  d_in[0];
    const int*   tgt  = (const int*)  d_in[1];
    const float* tok  = (const float*)d_in[2];
    const float* pos  = (const float*)d_in[3];
    const float* Wq   = (const float*)d_in[4];
    const float* Wk   = (const float*)d_in[5];
    const float* Wv   = (const float*)d_in[6];
    const float* Wo   = (const float*)d_in[7];
    const float* bo   = (const float*)d_in[8];
    const float* ln1g = (const float*)d_in[9];
    const float* ln1b = (const float*)d_in[10];
    const float* W1   = (const float*)d_in[11];
    const float* b1   = (const float*)d_in[12];
    const float* W2   = (const float*)d_in[13];
    const float* b2   = (const float*)d_in[14];
    const float* ln2g = (const float*)d_in[15];
    const float* ln2b = (const float*)d_in[16];
    const float* lnfg = (const float*)d_in[17];
    const float* lnfb = (const float*)d_in[18];
    const float* lmw  = (const float*)d_in[19];
    const float* lmb  = (const float*)d_in[20];

    float *x, *y, *qkv, *att, *hbuf, *lscratch, *tokloss;
    __nv_bfloat16 *ah, *al, *wh, *wl, *wqh, *wql;
    cudaGetSymbolAddress((void**)&x,        g_x);
    cudaGetSymbolAddress((void**)&y,        g_y);
    cudaGetSymbolAddress((void**)&qkv,      g_qkv);
    cudaGetSymbolAddress((void**)&att,      g_att);
    cudaGetSymbolAddress((void**)&hbuf,     g_h);
    cudaGetSymbolAddress((void**)&lscratch, g_logits);
    cudaGetSymbolAddress((void**)&tokloss,  g_tokloss);
    cudaGetSymbolAddress((void**)&ah,       g_ah);
    cudaGetSymbolAddress((void**)&al,       g_al);
    cudaGetSymbolAddress((void**)&wh,       g_wh);
    cudaGetSymbolAddress((void**)&wl,       g_wl);
    cudaGetSymbolAddress((void**)&wqh,      g_wqh);
    cudaGetSymbolAddress((void**)&wql,      g_wql);

    const size_t LOG_N = (size_t)BT_ * V_;
    float* logits_ptr = ((size_t)out_size >= LOG_N) ? (float*)d_out : lscratch;
    float* loss_ptr = nullptr;
    if ((size_t)out_size >= LOG_N + 1) loss_ptr = (float*)d_out + LOG_N;
    else if ((size_t)out_size < LOG_N) loss_ptr = (float*)d_out;

    cudaFuncSetAttribute(attn_kernel, cudaFuncAttributeMaxDynamicSharedMemorySize,
                         ATTN_SMEM_BYTES);
    cudaFuncSetAttribute(gemm_mm<0>,
                         cudaFuncAttributeMaxDynamicSharedMemorySize, SMEM_MM);
    cudaFuncSetAttribute(gemm_mm<EPI_BIAS|EPI_RES>,
                         cudaFuncAttributeMaxDynamicSharedMemorySize, SMEM_MM);
    cudaFuncSetAttribute(gemm_mm<EPI_BIAS|EPI_GELU>,
                         cudaFuncAttributeMaxDynamicSharedMemorySize, SMEM_MM);
    cudaFuncSetAttribute(gemm_mm<EPI_BIAS>,
                         cudaFuncAttributeMaxDynamicSharedMemorySize, SMEM_MM);

    embed_kernel<<<BT_*(E_/4)/256, 256>>>(idx, tok, pos, x);

    for (int l = 0; l < NL_; l++) {
        // QKV via HMMA: qkv[131072, 256] = x[131072, 64] @ Wqkv[256, 64]^T
        cvt_kernel<<<(BT_*E_/4)/256, 256>>>(x, ah, al, BT_*E_/4);
        pack_qkv_kernel<<<64, 256>>>(Wq + (size_t)l*DH_*DH_,
                                     Wk + (size_t)l*DH_*DH_,
                                     Wv + (size_t)l*DH_*DH_, wqh, wql);
        gemm_mm<0><<<dim3(MQKV_/128, 2), 512, SMEM_MM>>>(
            ah, al, wqh, wql, nullptr, nullptr, qkv, MQKV_, 256, 64);

        attn_kernel<<<dim3(T_/64, B_*H_), 256, ATTN_SMEM_BYTES>>>(qkv, att);

        // out-proj: y = att @ Wo^T + bo + x
        cvt_kernel<<<(BT_*E_/4)/256, 256>>>(att, ah, al, BT_*E_/4);
        cvt_kernel<<<(E_*E_/4)/256, 256>>>(Wo + (size_t)l*E_*E_, wh, wl, E_*E_/4);
        gemm_mm<EPI_BIAS|EPI_RES><<<dim3(BT_/128, E_/128), 512, SMEM_MM>>>(
            ah, al, wh, wl, bo + (size_t)l*E_, x, y, BT_, E_, E_);
        ln_kernel<<<BT_, 256>>>(y, ln1g + (size_t)l*E_, ln1b + (size_t)l*E_, x);

        // FF1: h = gelu(x @ W1^T + b1)
        cvt_kernel<<<(BT_*E_/4)/256, 256>>>(x, ah, al, BT_*E_/4);
        cvt_kernel<<<(FF_*E_/4)/256, 256>>>(W1 + (size_t)l*FF_*E_, wh, wl, FF_*E_/4);
        gemm_mm<EPI_BIAS|EPI_GELU><<<dim3(BT_/128, FF_/128), 512, SMEM_MM>>>(
            ah, al, wh, wl, b1 + (size_t)l*FF_, nullptr, hbuf, BT_, FF_, E_);

        // FF2: y = h @ W2^T + b2 + x
        cvt_kernel<<<((size_t)BT_*FF_/4)/256, 256>>>(hbuf, ah, al, BT_*FF_/4);
        cvt_kernel<<<(E_*FF_/4)/256, 256>>>(W2 + (size_t)l*E_*FF_, wh, wl, E_*FF_/4);
        gemm_mm<EPI_BIAS|EPI_RES><<<dim3(BT_/128, E_/128), 512, SMEM_MM>>>(
            ah, al, wh, wl, b2 + (size_t)l*E_, x, y, BT_, E_, FF_);
        ln_kernel<<<BT_, 256>>>(y, ln2g + (size_t)l*E_, ln2b + (size_t)l*E_, x);
    }

    ln_kernel<<<BT_, 256>>>(x, lnfg, lnfb, y);

    // LM head
    cvt_kernel<<<(BT_*E_/4)/256, 256>>>(y, ah, al, BT_*E_/4);
    cvt_kernel<<<((size_t)V_*E_/4)/256, 256>>>(lmw, wh, wl, V_*E_/4);
    gemm_mm<EPI_BIAS><<<dim3(BT_/128, V_/128), 512, SMEM_MM>>>(
        ah, al, wh, wl, lmb, nullptr, logits_ptr, BT_, V_, E_);

    if (loss_ptr) {
        loss_tok_kernel<<<BT_, 256>>>(logits_ptr, tgt, tokloss);
        loss_reduce_kernel<<<1, 256>>>(tokloss, loss_ptr);
    }
}

// round 13
// speedup vs baseline: 1.0631x; 1.0631x over previous
#include <cuda_runtime.h>
#include <cuda_bf16.h>
#include <math.h>
#include <stdint.h>

#define B_  4
#define T_  2048
#define E_  1024
#define H_  16
#define DH_ 64
#define NL_ 4
#define FF_ 4096
#define V_  32000
#define BT_ (B_*T_)        // 8192 tokens
#define MQKV_ (BT_*H_)     // 131072 per-head rows

// ---------------- scratch (static device allocations; no cudaMalloc) -------
__device__ float g_x[BT_*E_];
__device__ float g_y[BT_*E_];
__device__ float g_qkv[(size_t)MQKV_*256];   // packed q|k|v|pad, row stride 256
__device__ float g_logits[(size_t)BT_*V_];
__device__ float g_tokloss[BT_];
// bf16 hi/lo split buffers
__device__ __nv_bfloat16 g_xh[BT_*E_];       // activation split (x / attn-out)
__device__ __nv_bfloat16 g_xl[BT_*E_];
__device__ __nv_bfloat16 g_hh[(size_t)BT_*FF_];  // FF1 output split
__device__ __nv_bfloat16 g_hl[(size_t)BT_*FF_];
__device__ __nv_bfloat16 g_wh[(size_t)V_*E_];    // weight split
__device__ __nv_bfloat16 g_wl[(size_t)V_*E_];
__device__ __nv_bfloat16 g_wqh[256*64];
__device__ __nv_bfloat16 g_wql[256*64];

// ======================= low-level helpers =================================
__device__ __forceinline__ uint32_t smem_u32(const void* p) {
    uint32_t a;
    asm("{ .reg .u64 t; cvta.to.shared.u64 t, %1; cvt.u32.u64 %0, t; }"
        : "=r"(a) : "l"(p));
    return a;
}
__device__ __forceinline__ void cp16(uint32_t dst, const void* src) {
    asm volatile("cp.async.cg.shared.global [%0], [%1], 16;\n"
                 :: "r"(dst), "l"(src));
}
__device__ __forceinline__ void cp_commit() {
    asm volatile("cp.async.commit_group;" ::: "memory");
}
__device__ __forceinline__ void cp_wait2() {
    asm volatile("cp.async.wait_group 2;" ::: "memory");
}
#define LDSM4(r0,r1,r2,r3,addr) \
    asm volatile("ldmatrix.sync.aligned.m8n8.x4.shared.b16 {%0,%1,%2,%3}, [%4];" \
        : "=r"(r0),"=r"(r1),"=r"(r2),"=r"(r3) : "r"(addr))
#define MMA16816(c,a,b) \
    asm volatile("mma.sync.aligned.m16n8k16.row.col.f32.bf16.bf16.f32 " \
        "{%0,%1,%2,%3}, {%4,%5,%6,%7}, {%8,%9}, {%0,%1,%2,%3};" \
        : "+f"((c)[0]),"+f"((c)[1]),"+f"((c)[2]),"+f"((c)[3]) \
        : "r"((a)[0]),"r"((a)[1]),"r"((a)[2]),"r"((a)[3]), \
          "r"((b)[0]),"r"((b)[1]))

// ======================= bf16 hi/lo HMMA GEMM ==============================
// C[M,N] = (Ah+Al)[M,K] @ (Bh+Bl)[N,K]^T, fp32 acc, 3-pass split precision.
// CTA tile 256x128, K-chunk 32, 16 warps (8M x 2N, warp tile 32x64),
// 3-stage cp.async pipeline, 80B-padded smem rows (conflict-free ldmatrix).
#define EPI_BIAS  1
#define EPI_RES   2
#define EPI_GELU  4
#define EPI_SPLIT 8

#define PAD_ROW 80                    // bytes per smem row: 64B data + 16B pad
#define A_TILE  (256*PAD_ROW)         // 20480
#define B_TILE  (128*PAD_ROW)         // 10240
#define S_AH 0
#define S_AL (A_TILE)
#define S_BH (2*A_TILE)
#define S_BL (2*A_TILE + B_TILE)
#define STAGE_MM (2*A_TILE + 2*B_TILE)   // 61440
#define SMEM_MM  (3*STAGE_MM)            // 184320

__device__ __forceinline__ void mm_load(
    uint32_t st, const __nv_bfloat16* __restrict__ Ah,
    const __nv_bfloat16* __restrict__ Al,
    const __nv_bfloat16* __restrict__ Bh,
    const __nv_bfloat16* __restrict__ Bl,
    int m0, int n0, int K, int k0, int tid)
{
    #pragma unroll
    for (int j = 0; j < 2; j++) {
        int idx = tid + j * 512;          // 0..1023
        int row = idx >> 2;               // 0..255
        int c16 = idx & 3;
        uint32_t so = row * PAD_ROW + c16 * 16;
        size_t go = (size_t)(m0 + row) * K + k0 + c16 * 8;
        cp16(st + S_AH + so, Ah + go);
        cp16(st + S_AL + so, Al + go);
    }
    {
        int row = tid >> 2;               // 0..127
        int c16 = tid & 3;
        uint32_t so = row * PAD_ROW + c16 * 16;
        size_t go = (size_t)(n0 + row) * K + k0 + c16 * 8;
        cp16(st + S_BH + so, Bh + go);
        cp16(st + S_BL + so, Bl + go);
    }
}

template<int EPI>
__global__ void __launch_bounds__(512) gemm_mm(
    const __nv_bfloat16* __restrict__ Ah, const __nv_bfloat16* __restrict__ Al,
    const __nv_bfloat16* __restrict__ Bh, const __nv_bfloat16* __restrict__ Bl,
    const float* __restrict__ bias, const float* __restrict__ res,
    float* __restrict__ C, __nv_bfloat16* __restrict__ Ch,
    __nv_bfloat16* __restrict__ Cl, int M, int N, int K)
{
    extern __shared__ char smraw[];
    const uint32_t sb = smem_u32(smraw);
    const int tid  = threadIdx.x;
    const int lane = tid & 31;
    const int wid  = tid >> 5;            // 0..15
    const int wm = (wid & 7) * 32;        // warp M offset (8 warps along M)
    const int wn = (wid >> 3) * 64;       // warp N offset (2 warps along N)
    const int m0 = blockIdx.x * 256;
    const int n0 = blockIdx.y * 128;
    const int NC = K >> 5;                // chunks of 32 (always >= 2)

    float c[2][8][4];
    #pragma unroll
    for (int i = 0; i < 2; i++)
        #pragma unroll
        for (int j = 0; j < 8; j++)
            #pragma unroll
            for (int r = 0; r < 4; r++) c[i][j][r] = 0.f;

    // ldmatrix per-lane address components
    const int a_row = wm + (lane & 15);                       // mi adds 16
    const int a_kof = (lane >> 4) * 8;
    const int b_row = wn + (lane & 7) + ((lane >> 4) & 1) * 8; // nj adds 8*nj
    const int b_kof = ((lane >> 3) & 1) * 8;

    mm_load(sb,            Ah, Al, Bh, Bl, m0, n0, K, 0,  tid);
    cp_commit();
    mm_load(sb + STAGE_MM, Ah, Al, Bh, Bl, m0, n0, K, 32, tid);
    cp_commit();

    for (int ck = 0; ck < NC; ck++) {
        if (ck + 2 < NC)
            mm_load(sb + ((ck + 2) % 3) * STAGE_MM, Ah, Al, Bh, Bl,
                    m0, n0, K, (ck + 2) << 5, tid);
        cp_commit();          // one group per iter (may be empty)
        cp_wait2();           // chunk ck resident
        __syncthreads();

        const uint32_t st = sb + (ck % 3) * STAGE_MM;
        #pragma unroll
        for (int ks = 0; ks < 2; ks++) {
            const int k0 = ks * 16;
            uint32_t ah[2][4], al[2][4], bh[8][2], bl[8][2];
            #pragma unroll
            for (int mi = 0; mi < 2; mi++) {
                uint32_t ad = st + (a_row + mi * 16) * PAD_ROW + (k0 + a_kof) * 2;
                LDSM4(ah[mi][0], ah[mi][1], ah[mi][2], ah[mi][3], ad + S_AH);
                LDSM4(al[mi][0], al[mi][1], al[mi][2], al[mi][3], ad + S_AL);
            }
            #pragma unroll
            for (int nj = 0; nj < 8; nj += 2) {
                uint32_t bd = st + (b_row + nj * 8) * PAD_ROW + (k0 + b_kof) * 2;
                LDSM4(bh[nj][0], bh[nj][1], bh[nj+1][0], bh[nj+1][1], bd + S_BH);
                LDSM4(bl[nj][0], bl[nj][1], bl[nj+1][0], bl[nj+1][1], bd + S_BL);
            }
            // 3 passes swept over all 16 fragments (RAW distance = 16)
            #pragma unroll
            for (int mi = 0; mi < 2; mi++)
                #pragma unroll
                for (int ni = 0; ni < 8; ni++)
                    MMA16816(c[mi][ni], ah[mi], bh[ni]);
            #pragma unroll
            for (int mi = 0; mi < 2; mi++)
                #pragma unroll
                for (int ni = 0; ni < 8; ni++)
                    MMA16816(c[mi][ni], ah[mi], bl[ni]);
            #pragma unroll
            for (int mi = 0; mi < 2; mi++)
                #pragma unroll
                for (int ni = 0; ni < 8; ni++)
                    MMA16816(c[mi][ni], al[mi], bh[ni]);
        }
        __syncthreads();
    }

    // epilogue: c frag rows = lane>>2 (+8), cols = 2*(lane&3) (+1)
    #pragma unroll
    for (int mi = 0; mi < 2; mi++) {
        const int mr = m0 + wm + mi * 16 + (lane >> 2);
        #pragma unroll
        for (int half = 0; half < 2; half++) {
            const int m = mr + half * 8;
            #pragma unroll
            for (int ni = 0; ni < 8; ni++) {
                const int n = n0 + wn + ni * 8 + 2 * (lane & 3);
                float v0 = c[mi][ni][half * 2 + 0];
                float v1 = c[mi][ni][half * 2 + 1];
                if (EPI & EPI_BIAS) { v0 += bias[n]; v1 += bias[n + 1]; }
                if (EPI & EPI_RES) {
                    float2 r2 = *(const float2*)(res + (size_t)m * N + n);
                    v0 += r2.x; v1 += r2.y;
                }
                if (EPI & EPI_GELU) {
                    v0 = 0.5f * v0 * (1.f + erff(v0 * 0.70710678118654752f));
                    v1 = 0.5f * v1 * (1.f + erff(v1 * 0.70710678118654752f));
                }
                if (EPI & EPI_SPLIT) {
                    __nv_bfloat16 h0 = __float2bfloat16(v0);
                    __nv_bfloat16 h1 = __float2bfloat16(v1);
                    __nv_bfloat16 l0 = __float2bfloat16(v0 - __bfloat162float(h0));
                    __nv_bfloat16 l1 = __float2bfloat16(v1 - __bfloat162float(h1));
                    *(__nv_bfloat162*)(Ch + (size_t)m * N + n) = __nv_bfloat162(h0, h1);
                    *(__nv_bfloat162*)(Cl + (size_t)m * N + n) = __nv_bfloat162(l0, l1);
                } else {
                    *(float2*)(C + (size_t)m * N + n) = make_float2(v0, v1);
                }
            }
        }
    }
}

// ---------------- fp32 -> bf16 hi/lo conversion (weights) ------------------
__global__ void __launch_bounds__(256) cvt_kernel(
    const float* __restrict__ in, __nv_bfloat16* __restrict__ hi,
    __nv_bfloat16* __restrict__ lo, int n4)
{
    int i = blockIdx.x * 256 + threadIdx.x;
    if (i >= n4) return;
    float4 x = ((const float4*)in)[i];
    __nv_bfloat16 h0 = __float2bfloat16(x.x);
    __nv_bfloat16 h1 = __float2bfloat16(x.y);
    __nv_bfloat16 h2 = __float2bfloat16(x.z);
    __nv_bfloat16 h3 = __float2bfloat16(x.w);
    __nv_bfloat16 l0 = __float2bfloat16(x.x - __bfloat162float(h0));
    __nv_bfloat16 l1 = __float2bfloat16(x.y - __bfloat162float(h1));
    __nv_bfloat16 l2 = __float2bfloat16(x.z - __bfloat162float(h2));
    __nv_bfloat16 l3 = __float2bfloat16(x.w - __bfloat162float(h3));
    ((__nv_bfloat162*)hi)[2*i]   = __nv_bfloat162(h0, h1);
    ((__nv_bfloat162*)hi)[2*i+1] = __nv_bfloat162(h2, h3);
    ((__nv_bfloat162*)lo)[2*i]   = __nv_bfloat162(l0, l1);
    ((__nv_bfloat162*)lo)[2*i+1] = __nv_bfloat162(l2, l3);
}

// ---------------- pack Wq|Wk|Wv -> padded [256 x 64] bf16 hi/lo ------------
__global__ void __launch_bounds__(256) pack_qkv_kernel(
    const float* __restrict__ Wq, const float* __restrict__ Wk,
    const float* __restrict__ Wv,
    __nv_bfloat16* __restrict__ wh, __nv_bfloat16* __restrict__ wl)
{
    int i = blockIdx.x * 256 + threadIdx.x;   // 0..16383
    int row = i >> 6, col = i & 63;
    float v = 0.f;
    if (row < 64)       v = Wq[row * 64 + col];
    else if (row < 128) v = Wk[(row - 64) * 64 + col];
    else if (row < 192) v = Wv[(row - 128) * 64 + col];
    __nv_bfloat16 h = __float2bfloat16(v);
    wh[i] = h;
    wl[i] = __float2bfloat16(v - __bfloat162float(h));
}

// ---------------- flash attention (causal, online softmax, fp32) -----------
// reads packed qkv rows of stride 256: [q(64) | k(64) | v(64) | pad(64)]
// writes bf16 hi/lo split of the output (feeds the Wo GEMM directly)
#define ATTN_SMEM_FLOATS (4*64*65 + 3*64)
#define ATTN_SMEM_BYTES  (ATTN_SMEM_FLOATS * 4)

__global__ void __launch_bounds__(256) attn_kernel(
    const float* __restrict__ qkv,
    __nv_bfloat16* __restrict__ oh, __nv_bfloat16* __restrict__ ol)
{
    extern __shared__ float sm[];
    float* Qs  = sm;
    float* Ks  = sm + 64*65;
    float* Vs  = sm + 2*64*65;
    float* Ps  = sm + 3*64*65;
    float* m_s = sm + 4*64*65;
    float* l_s = m_s + 64;
    float* al_s= l_s + 64;

    const int qt = blockIdx.x;
    const int bh = blockIdx.y;
    const int b  = bh / H_, h = bh % H_;
    const int q0 = qt * 64;
    const int tid = threadIdx.x;
    const int tx = tid & 15, ty = tid >> 4;

    {
        int r  = tid >> 2;
        int c0 = (tid & 3) * 16;
        const float* src = qkv + ((size_t)(b * T_ + q0 + r) * H_ + h) * 256 + c0;
        #pragma unroll
        for (int j = 0; j < 4; j++) {
            float4 t4 = *(const float4*)(src + j*4);
            Qs[r*65 + c0 + j*4 + 0] = t4.x;
            Qs[r*65 + c0 + j*4 + 1] = t4.y;
            Qs[r*65 + c0 + j*4 + 2] = t4.z;
            Qs[r*65 + c0 + j*4 + 3] = t4.w;
        }
    }
    if (tid < 64) { m_s[tid] = -1e30f; l_s[tid] = 0.f; }

    float o[4][4];
    #pragma unroll
    for (int i = 0; i < 4; i++)
        #pragma unroll
        for (int j = 0; j < 4; j++) o[i][j] = 0.f;

    for (int kt = 0; kt <= qt; kt++) {
        const int k0 = kt * 64;
        __syncthreads();
        {
            int r  = tid >> 2;
            int c0 = (tid & 3) * 16;
            const float* base = qkv + ((size_t)(b * T_ + k0 + r) * H_ + h) * 256;
            #pragma unroll
            for (int j = 0; j < 4; j++) {
                float4 t4 = *(const float4*)(base + 64 + c0 + j*4);
                Ks[r*65+c0+j*4+0] = t4.x; Ks[r*65+c0+j*4+1] = t4.y;
                Ks[r*65+c0+j*4+2] = t4.z; Ks[r*65+c0+j*4+3] = t4.w;
                float4 u4 = *(const float4*)(base + 128 + c0 + j*4);
                Vs[r*65+c0+j*4+0] = u4.x; Vs[r*65+c0+j*4+1] = u4.y;
                Vs[r*65+c0+j*4+2] = u4.z; Vs[r*65+c0+j*4+3] = u4.w;
            }
        }
        __syncthreads();

        float s[4][4];
        #pragma unroll
        for (int i = 0; i < 4; i++)
            #pragma unroll
            for (int j = 0; j < 4; j++) s[i][j] = 0.f;
        for (int d = 0; d < 64; d++) {
            float a[4], bb[4];
            #pragma unroll
            for (int i = 0; i < 4; i++) a[i]  = Qs[(ty*4+i)*65 + d];
            #pragma unroll
            for (int j = 0; j < 4; j++) bb[j] = Ks[(tx*4+j)*65 + d];
            #pragma unroll
            for (int i = 0; i < 4; i++)
                #pragma unroll
                for (int j = 0; j < 4; j++)
                    s[i][j] = fmaf(a[i], bb[j], s[i][j]);
        }
        const bool diag = (kt == qt);
        #pragma unroll
        for (int i = 0; i < 4; i++)
            #pragma unroll
            for (int j = 0; j < 4; j++) {
                float val = s[i][j] * 0.125f;
                if (diag && (tx*4+j) > (ty*4+i)) val = -1e30f;
                Ps[(ty*4+i)*65 + tx*4+j] = val;
            }
        __syncthreads();

        {
            int r  = tid >> 2;
            int c0 = (tid & 3) * 16;
            float mx = -1e30f;
            for (int c = 0; c < 16; c++) mx = fmaxf(mx, Ps[r*65 + c0 + c]);
            mx = fmaxf(mx, __shfl_xor_sync(0xffffffffu, mx, 1));
            mx = fmaxf(mx, __shfl_xor_sync(0xffffffffu, mx, 2));
            float m_old = m_s[r];
            float m_new = fmaxf(m_old, mx);
            float ssum = 0.f;
            for (int c = 0; c < 16; c++) {
                float p = __expf(Ps[r*65 + c0 + c] - m_new);
                Ps[r*65 + c0 + c] = p;
                ssum += p;
            }
            ssum += __shfl_xor_sync(0xffffffffu, ssum, 1);
            ssum += __shfl_xor_sync(0xffffffffu, ssum, 2);
            if ((tid & 3) == 0) {
                float alpha = __expf(m_old - m_new);
                al_s[r] = alpha;
                m_s[r]  = m_new;
                l_s[r]  = l_s[r] * alpha + ssum;
            }
        }
        __syncthreads();

        float al[4];
        #pragma unroll
        for (int i = 0; i < 4; i++) al[i] = al_s[ty*4+i];
        #pragma unroll
        for (int i = 0; i < 4; i++)
            #pragma unroll
            for (int j = 0; j < 4; j++) o[i][j] *= al[i];
        for (int c = 0; c < 64; c++) {
            float p[4], vv[4];
            #pragma unroll
            for (int i = 0; i < 4; i++) p[i]  = Ps[(ty*4+i)*65 + c];
            #pragma unroll
            for (int j = 0; j < 4; j++) vv[j] = Vs[c*65 + tx*4+j];
            #pragma unroll
            for (int i = 0; i < 4; i++)
                #pragma unroll
                for (int j = 0; j < 4; j++)
                    o[i][j] = fmaf(p[i], vv[j], o[i][j]);
        }
    }

    #pragma unroll
    for (int i = 0; i < 4; i++) {
        int r = ty*4 + i;
        float inv = 1.0f / l_s[r];
        size_t base = ((size_t)(b * T_ + q0 + r) * H_ + h) * DH_ + tx*4;
        #pragma unroll
        for (int jj = 0; jj < 2; jj++) {
            float v0 = o[i][jj*2+0] * inv;
            float v1 = o[i][jj*2+1] * inv;
            __nv_bfloat16 h0 = __float2bfloat16(v0);
            __nv_bfloat16 h1 = __float2bfloat16(v1);
            __nv_bfloat16 l0 = __float2bfloat16(v0 - __bfloat162float(h0));
            __nv_bfloat16 l1 = __float2bfloat16(v1 - __bfloat162float(h1));
            *(__nv_bfloat162*)(oh + base + jj*2) = __nv_bfloat162(h0, h1);
            *(__nv_bfloat162*)(ol + base + jj*2) = __nv_bfloat162(l0, l1);
        }
    }
}

// ---------------- layernorm (+ fused bf16 hi/lo split output) --------------
__global__ void __launch_bounds__(256) ln_kernel(
    const float* __restrict__ in, const float* __restrict__ gg,
    const float* __restrict__ bb, float* __restrict__ out,
    __nv_bfloat16* __restrict__ oh, __nv_bfloat16* __restrict__ ol)
{
    __shared__ float red[8];
    const int row = blockIdx.x;
    const int tid = threadIdx.x;
    float4 vx = ((const float4*)(in + (size_t)row * E_))[tid];
    float s = vx.x + vx.y + vx.z + vx.w;
    #pragma unroll
    for (int o = 16; o; o >>= 1) s += __shfl_xor_sync(0xffffffffu, s, o);
    if ((tid & 31) == 0) red[tid >> 5] = s;
    __syncthreads();
    float mean = (red[0]+red[1]+red[2]+red[3]+red[4]+red[5]+red[6]+red[7]) * (1.f/E_);
    __syncthreads();
    float dx = vx.x - mean, dy = vx.y - mean, dz = vx.z - mean, dw = vx.w - mean;
    float s2 = dx*dx + dy*dy + dz*dz + dw*dw;
    #pragma unroll
    for (int o = 16; o; o >>= 1) s2 += __shfl_xor_sync(0xffffffffu, s2, o);
    if ((tid & 31) == 0) red[tid >> 5] = s2;
    __syncthreads();
    float var = (red[0]+red[1]+red[2]+red[3]+red[4]+red[5]+red[6]+red[7]) * (1.f/E_);
    float rstd = rsqrtf(var + 1e-5f);
    float4 g4 = ((const float4*)gg)[tid];
    float4 b4 = ((const float4*)bb)[tid];
    float4 o4 = make_float4(dx*rstd*g4.x + b4.x, dy*rstd*g4.y + b4.y,
                            dz*rstd*g4.z + b4.z, dw*rstd*g4.w + b4.w);
    ((float4*)(out + (size_t)row * E_))[tid] = o4;
    __nv_bfloat16 h0 = __float2bfloat16(o4.x);
    __nv_bfloat16 h1 = __float2bfloat16(o4.y);
    __nv_bfloat16 h2 = __float2bfloat16(o4.z);
    __nv_bfloat16 h3 = __float2bfloat16(o4.w);
    __nv_bfloat16 l0 = __float2bfloat16(o4.x - __bfloat162float(h0));
    __nv_bfloat16 l1 = __float2bfloat16(o4.y - __bfloat162float(h1));
    __nv_bfloat16 l2 = __float2bfloat16(o4.z - __bfloat162float(h2));
    __nv_bfloat16 l3 = __float2bfloat16(o4.w - __bfloat162float(h3));
    __nv_bfloat162* ph = (__nv_bfloat162*)(oh + (size_t)row * E_);
    __nv_bfloat162* pl = (__nv_bfloat162*)(ol + (size_t)row * E_);
    ph[tid*2]   = __nv_bfloat162(h0, h1);
    ph[tid*2+1] = __nv_bfloat162(h2, h3);
    pl[tid*2]   = __nv_bfloat162(l0, l1);
    pl[tid*2+1] = __nv_bfloat162(l2, l3);
}

// ---------------- token+pos embedding (+ split) -----------------------------
__global__ void __launch_bounds__(256) embed_kernel(
    const int* __restrict__ idx, const float* __restrict__ tok,
    const float* __restrict__ pos, float* __restrict__ out,
    __nv_bfloat16* __restrict__ oh, __nv_bfloat16* __restrict__ ol)
{
    int gid = blockIdx.x * 256 + threadIdx.x;
    int e4 = gid & (E_/4 - 1);
    int bt = gid >> 8;
    int t  = bt & (T_ - 1);
    int token = idx[bt];
    float4 a = ((const float4*)(tok + (size_t)token * E_))[e4];
    float4 p = ((const float4*)(pos + (size_t)t * E_))[e4];
    float4 v = make_float4(a.x+p.x, a.y+p.y, a.z+p.z, a.w+p.w);
    ((float4*)out)[gid] = v;
    __nv_bfloat16 h0 = __float2bfloat16(v.x);
    __nv_bfloat16 h1 = __float2bfloat16(v.y);
    __nv_bfloat16 h2 = __float2bfloat16(v.z);
    __nv_bfloat16 h3 = __float2bfloat16(v.w);
    __nv_bfloat16 l0 = __float2bfloat16(v.x - __bfloat162float(h0));
    __nv_bfloat16 l1 = __float2bfloat16(v.y - __bfloat162float(h1));
    __nv_bfloat16 l2 = __float2bfloat16(v.z - __bfloat162float(h2));
    __nv_bfloat16 l3 = __float2bfloat16(v.w - __bfloat162float(h3));
    ((__nv_bfloat162*)oh)[2*gid]   = __nv_bfloat162(h0, h1);
    ((__nv_bfloat162*)oh)[2*gid+1] = __nv_bfloat162(h2, h3);
    ((__nv_bfloat162*)ol)[2*gid]   = __nv_bfloat162(l0, l1);
    ((__nv_bfloat162*)ol)[2*gid+1] = __nv_bfloat162(l2, l3);
}

// ---------------- loss -----------------------------------------------------
__global__ void __launch_bounds__(256) loss_tok_kernel(
    const float* __restrict__ logits, const int* __restrict__ targets,
    float* __restrict__ tokloss)
{
    __shared__ float red[8];
    const int row = blockIdx.x;
    const int tid = threadIdx.x;
    const float* lg = logits + (size_t)row * V_;
    float mx = -1e30f;
    for (int i = tid; i < V_; i += 256) mx = fmaxf(mx, lg[i]);
    #pragma unroll
    for (int o = 16; o; o >>= 1) mx = fmaxf(mx, __shfl_xor_sync(0xffffffffu, mx, o));
    if ((tid & 31) == 0) red[tid >> 5] = mx;
    __syncthreads();
    mx = fmaxf(fmaxf(fmaxf(red[0], red[1]), fmaxf(red[2], red[3])),
               fmaxf(fmaxf(red[4], red[5]), fmaxf(red[6], red[7])));
    __syncthreads();
    float s = 0.f;
    for (int i = tid; i < V_; i += 256) s += __expf(lg[i] - mx);
    #pragma unroll
    for (int o = 16; o; o >>= 1) s += __shfl_xor_sync(0xffffffffu, s, o);
    if ((tid & 31) == 0) red[tid >> 5] = s;
    __syncthreads();
    if (tid == 0) {
        float tot = red[0]+red[1]+red[2]+red[3]+red[4]+red[5]+red[6]+red[7];
        tokloss[row] = -(lg[targets[row]] - mx - logf(tot));
    }
}

__global__ void __launch_bounds__(256) loss_reduce_kernel(
    const float* __restrict__ tokloss, float* __restrict__ outp)
{
    __shared__ float red[8];
    const int tid = threadIdx.x;
    float s = 0.f;
    for (int i = tid; i < BT_; i += 256) s += tokloss[i];
    #pragma unroll
    for (int o = 16; o; o >>= 1) s += __shfl_xor_sync(0xffffffffu, s, o);
    if ((tid & 31) == 0) red[tid >> 5] = s;
    __syncthreads();
    if (tid == 0) {
        float tot = red[0]+red[1]+red[2]+red[3]+red[4]+red[5]+red[6]+red[7];
        outp[0] = tot / (float)BT_;
    }
}

// ---------------- host driver ----------------------------------------------
extern "C" void kernel_launch(void* const* d_in, const int* in_sizes, int n_in,
                              void* d_out, int out_size)
{
    const int*   idx  = (const int*)  d_in[0];
    const int*   tgt  = (const int*)  d_in[1];
    const float* tok  = (const float*)d_in[2];
    const float* pos  = (const float*)d_in[3];
    const float* Wq   = (const float*)d_in[4];
    const float* Wk   = (const float*)d_in[5];
    const float* Wv   = (const float*)d_in[6];
    const float* Wo   = (const float*)d_in[7];
    const float* bo   = (const float*)d_in[8];
    const float* ln1g = (const float*)d_in[9];
    const float* ln1b = (const float*)d_in[10];
    const float* W1   = (const float*)d_in[11];
    const float* b1   = (const float*)d_in[12];
    const float* W2   = (const float*)d_in[13];
    const float* b2   = (const float*)d_in[14];
    const float* ln2g = (const float*)d_in[15];
    const float* ln2b = (const float*)d_in[16];
    const float* lnfg = (const float*)d_in[17];
    const float* lnfb = (const float*)d_in[18];
    const float* lmw  = (const float*)d_in[19];
    const float* lmb  = (const float*)d_in[20];

    float *x, *y, *qkv, *lscratch, *tokloss;
    __nv_bfloat16 *xh, *xl, *hh, *hl, *wh, *wl, *wqh, *wql;
    cudaGetSymbolAddress((void**)&x,        g_x);
    cudaGetSymbolAddress((void**)&y,        g_y);
    cudaGetSymbolAddress((void**)&qkv,      g_qkv);
    cudaGetSymbolAddress((void**)&lscratch, g_logits);
    cudaGetSymbolAddress((void**)&tokloss,  g_tokloss);
    cudaGetSymbolAddress((void**)&xh,       g_xh);
    cudaGetSymbolAddress((void**)&xl,       g_xl);
    cudaGetSymbolAddress((void**)&hh,       g_hh);
    cudaGetSymbolAddress((void**)&hl,       g_hl);
    cudaGetSymbolAddress((void**)&wh,       g_wh);
    cudaGetSymbolAddress((void**)&wl,       g_wl);
    cudaGetSymbolAddress((void**)&wqh,      g_wqh);
    cudaGetSymbolAddress((void**)&wql,      g_wql);

    const size_t LOG_N = (size_t)BT_ * V_;
    float* logits_ptr = ((size_t)out_size >= LOG_N) ? (float*)d_out : lscratch;
    float* loss_ptr = nullptr;
    if ((size_t)out_size >= LOG_N + 1) loss_ptr = (float*)d_out + LOG_N;
    else if ((size_t)out_size < LOG_N) loss_ptr = (float*)d_out;

    cudaFuncSetAttribute(attn_kernel, cudaFuncAttributeMaxDynamicSharedMemorySize,
                         ATTN_SMEM_BYTES);
    cudaFuncSetAttribute(gemm_mm<0>,
                         cudaFuncAttributeMaxDynamicSharedMemorySize, SMEM_MM);
    cudaFuncSetAttribute(gemm_mm<EPI_BIAS|EPI_RES>,
                         cudaFuncAttributeMaxDynamicSharedMemorySize, SMEM_MM);
    cudaFuncSetAttribute(gemm_mm<EPI_BIAS|EPI_GELU|EPI_SPLIT>,
                         cudaFuncAttributeMaxDynamicSharedMemorySize, SMEM_MM);
    cudaFuncSetAttribute(gemm_mm<EPI_BIAS>,
                         cudaFuncAttributeMaxDynamicSharedMemorySize, SMEM_MM);

    embed_kernel<<<BT_*(E_/4)/256, 256>>>(idx, tok, pos, x, xh, xl);

    for (int l = 0; l < NL_; l++) {
        // QKV via HMMA: qkv[131072, 256] = x[131072, 64] @ Wqkv[256, 64]^T
        pack_qkv_kernel<<<64, 256>>>(Wq + (size_t)l*DH_*DH_,
                                     Wk + (size_t)l*DH_*DH_,
                                     Wv + (size_t)l*DH_*DH_, wqh, wql);
        gemm_mm<0><<<dim3(MQKV_/256, 2), 512, SMEM_MM>>>(
            xh, xl, wqh, wql, nullptr, nullptr, qkv, nullptr, nullptr,
            MQKV_, 256, 64);

        // attention writes bf16 split directly into xh/xl
        attn_kernel<<<dim3(T_/64, B_*H_), 256, ATTN_SMEM_BYTES>>>(qkv, xh, xl);

        // out-proj: y = att @ Wo^T + bo + x
        cvt_kernel<<<(E_*E_/4)/256, 256>>>(Wo + (size_t)l*E_*E_, wh, wl, E_*E_/4);
        gemm_mm<EPI_BIAS|EPI_RES><<<dim3(BT_/256, E_/128), 512, SMEM_MM>>>(
            xh, xl, wh, wl, bo + (size_t)l*E_, x, y, nullptr, nullptr,
            BT_, E_, E_);
        ln_kernel<<<BT_, 256>>>(y, ln1g + (size_t)l*E_, ln1b + (size_t)l*E_,
                                x, xh, xl);

        // FF1: h = gelu(x @ W1^T + b1), written directly as bf16 hi/lo
        cvt_kernel<<<(FF_*E_/4)/256, 256>>>(W1 + (size_t)l*FF_*E_, wh, wl, FF_*E_/4);
        gemm_mm<EPI_BIAS|EPI_GELU|EPI_SPLIT><<<dim3(BT_/256, FF_/128), 512, SMEM_MM>>>(
            xh, xl, wh, wl, b1 + (size_t)l*FF_, nullptr, nullptr, hh, hl,
            BT_, FF_, E_);

        // FF2: y = h @ W2^T + b2 + x
        cvt_kernel<<<(E_*FF_/4)/256, 256>>>(W2 + (size_t)l*E_*FF_, wh, wl, E_*FF_/4);
        gemm_mm<EPI_BIAS|EPI_RES><<<dim3(BT_/256, E_/128), 512, SMEM_MM>>>(
            hh, hl, wh, wl, b2 + (size_t)l*E_, x, y, nullptr, nullptr,
            BT_, E_, FF_);
        ln_kernel<<<BT_, 256>>>(y, ln2g + (size_t)l*E_, ln2b + (size_t)l*E_,
                                x, xh, xl);
    }

    ln_kernel<<<BT_, 256>>>(x, lnfg, lnfb, y, xh, xl);

    // LM head
    cvt_kernel<<<((size_t)V_*E_/4)/256, 256>>>(lmw, wh, wl, V_*E_/4);
    gemm_mm<EPI_BIAS><<<dim3(BT_/256, V_/128), 512, SMEM_MM>>>(
        xh, xl, wh, wl, lmb, nullptr, logits_ptr, nullptr, nullptr,
        BT_, V_, E_);

    if (loss_ptr) {
        loss_tok_kernel<<<BT_, 256>>>(logits_ptr, tgt, tokloss);
        loss_reduce_kernel<<<1, 256>>>(tokloss, loss_ptr);
    }
}

// round 14
// speedup vs baseline: 1.3895x; 1.3070x over previous
#include <cuda_runtime.h>
#include <cuda_bf16.h>
#include <math.h>
#include <stdint.h>

#define B_  4
#define T_  2048
#define E_  1024
#define H_  16
#define DH_ 64
#define NL_ 4
#define FF_ 4096
#define V_  32000
#define BT_ (B_*T_)        // 8192 tokens
#define MQKV_ (BT_*H_)     // 131072 per-head rows

// ---------------- scratch (static device allocations; no cudaMalloc) -------
__device__ float g_x[BT_*E_];
__device__ float g_y[BT_*E_];
__device__ float g_logits[(size_t)BT_*V_];
__device__ float g_tokloss[BT_];
// bf16 hi/lo split buffers
__device__ __nv_bfloat16 g_qkvh[(size_t)MQKV_*256];  // packed q|k|v|pad hi
__device__ __nv_bfloat16 g_qkvl[(size_t)MQKV_*256];  // packed q|k|v|pad lo
__device__ __nv_bfloat16 g_xh[BT_*E_];       // activation split (x / attn-out)
__device__ __nv_bfloat16 g_xl[BT_*E_];
__device__ __nv_bfloat16 g_hh[(size_t)BT_*FF_];  // FF1 output split
__device__ __nv_bfloat16 g_hl[(size_t)BT_*FF_];
__device__ __nv_bfloat16 g_wh[(size_t)V_*E_];    // weight split
__device__ __nv_bfloat16 g_wl[(size_t)V_*E_];
__device__ __nv_bfloat16 g_wqh[256*64];
__device__ __nv_bfloat16 g_wql[256*64];

// ======================= low-level helpers =================================
__device__ __forceinline__ uint32_t smem_u32(const void* p) {
    uint32_t a;
    asm("{ .reg .u64 t; cvta.to.shared.u64 t, %1; cvt.u32.u64 %0, t; }"
        : "=r"(a) : "l"(p));
    return a;
}
__device__ __forceinline__ void cp16(uint32_t dst, const void* src) {
    asm volatile("cp.async.cg.shared.global [%0], [%1], 16;\n"
                 :: "r"(dst), "l"(src));
}
__device__ __forceinline__ void cp_commit() {
    asm volatile("cp.async.commit_group;" ::: "memory");
}
__device__ __forceinline__ void cp_wait1() {
    asm volatile("cp.async.wait_group 1;" ::: "memory");
}
__device__ __forceinline__ void cp_wait2() {
    asm volatile("cp.async.wait_group 2;" ::: "memory");
}
#define LDSM4(r0,r1,r2,r3,addr) \
    asm volatile("ldmatrix.sync.aligned.m8n8.x4.shared.b16 {%0,%1,%2,%3}, [%4];" \
        : "=r"(r0),"=r"(r1),"=r"(r2),"=r"(r3) : "r"(addr))
#define LDSM4T(r0,r1,r2,r3,addr) \
    asm volatile("ldmatrix.sync.aligned.m8n8.x4.trans.shared.b16 {%0,%1,%2,%3}, [%4];" \
        : "=r"(r0),"=r"(r1),"=r"(r2),"=r"(r3) : "r"(addr))
#define MMA16816(c,a,b) \
    asm volatile("mma.sync.aligned.m16n8k16.row.col.f32.bf16.bf16.f32 " \
        "{%0,%1,%2,%3}, {%4,%5,%6,%7}, {%8,%9}, {%0,%1,%2,%3};" \
        : "+f"((c)[0]),"+f"((c)[1]),"+f"((c)[2]),"+f"((c)[3]) \
        : "r"((a)[0]),"r"((a)[1]),"r"((a)[2]),"r"((a)[3]), \
          "r"((b)[0]),"r"((b)[1]))

__device__ __forceinline__ void split2(float a, float b,
                                       uint32_t& hi, uint32_t& lo) {
    __nv_bfloat16 ha = __float2bfloat16(a), hb = __float2bfloat16(b);
    __nv_bfloat16 la = __float2bfloat16(a - __bfloat162float(ha));
    __nv_bfloat16 lb = __float2bfloat16(b - __bfloat162float(hb));
    __nv_bfloat162 th(ha, hb), tl(la, lb);
    hi = *(uint32_t*)&th; lo = *(uint32_t*)&tl;
}

// ======================= bf16 hi/lo HMMA GEMM ==============================
// C[M,N] = (Ah+Al)[M,K] @ (Bh+Bl)[N,K]^T, fp32 acc, 3-pass split precision.
// CTA tile 256x128, K-chunk 32, 16 warps (8M x 2N, warp tile 32x64),
// 3-stage cp.async pipeline, 80B-padded smem rows (conflict-free ldmatrix).
#define EPI_BIAS  1
#define EPI_RES   2
#define EPI_GELU  4
#define EPI_SPLIT 8

#define PAD_ROW 80                    // bytes per smem row: 64B data + 16B pad
#define A_TILE  (256*PAD_ROW)         // 20480
#define B_TILE  (128*PAD_ROW)         // 10240
#define S_AH 0
#define S_AL (A_TILE)
#define S_BH (2*A_TILE)
#define S_BL (2*A_TILE + B_TILE)
#define STAGE_MM (2*A_TILE + 2*B_TILE)   // 61440
#define SMEM_MM  (3*STAGE_MM)            // 184320

__device__ __forceinline__ void mm_load(
    uint32_t st, const __nv_bfloat16* __restrict__ Ah,
    const __nv_bfloat16* __restrict__ Al,
    const __nv_bfloat16* __restrict__ Bh,
    const __nv_bfloat16* __restrict__ Bl,
    int m0, int n0, int K, int k0, int tid)
{
    #pragma unroll
    for (int j = 0; j < 2; j++) {
        int idx = tid + j * 512;          // 0..1023
        int row = idx >> 2;               // 0..255
        int c16 = idx & 3;
        uint32_t so = row * PAD_ROW + c16 * 16;
        size_t go = (size_t)(m0 + row) * K + k0 + c16 * 8;
        cp16(st + S_AH + so, Ah + go);
        cp16(st + S_AL + so, Al + go);
    }
    {
        int row = tid >> 2;               // 0..127
        int c16 = tid & 3;
        uint32_t so = row * PAD_ROW + c16 * 16;
        size_t go = (size_t)(n0 + row) * K + k0 + c16 * 8;
        cp16(st + S_BH + so, Bh + go);
        cp16(st + S_BL + so, Bl + go);
    }
}

template<int EPI>
__global__ void __launch_bounds__(512) gemm_mm(
    const __nv_bfloat16* __restrict__ Ah, const __nv_bfloat16* __restrict__ Al,
    const __nv_bfloat16* __restrict__ Bh, const __nv_bfloat16* __restrict__ Bl,
    const float* __restrict__ bias, const float* __restrict__ res,
    float* __restrict__ C, __nv_bfloat16* __restrict__ Ch,
    __nv_bfloat16* __restrict__ Cl, int M, int N, int K)
{
    extern __shared__ char smraw[];
    const uint32_t sb = smem_u32(smraw);
    const int tid  = threadIdx.x;
    const int lane = tid & 31;
    const int wid  = tid >> 5;            // 0..15
    const int wm = (wid & 7) * 32;        // warp M offset (8 warps along M)
    const int wn = (wid >> 3) * 64;       // warp N offset (2 warps along N)
    const int m0 = blockIdx.x * 256;
    const int n0 = blockIdx.y * 128;
    const int NC = K >> 5;                // chunks of 32 (always >= 2)

    float c[2][8][4];
    #pragma unroll
    for (int i = 0; i < 2; i++)
        #pragma unroll
        for (int j = 0; j < 8; j++)
            #pragma unroll
            for (int r = 0; r < 4; r++) c[i][j][r] = 0.f;

    const int a_row = wm + (lane & 15);
    const int a_kof = (lane >> 4) * 8;
    const int b_row = wn + (lane & 7) + ((lane >> 4) & 1) * 8;
    const int b_kof = ((lane >> 3) & 1) * 8;

    mm_load(sb,            Ah, Al, Bh, Bl, m0, n0, K, 0,  tid);
    cp_commit();
    mm_load(sb + STAGE_MM, Ah, Al, Bh, Bl, m0, n0, K, 32, tid);
    cp_commit();

    for (int ck = 0; ck < NC; ck++) {
        if (ck + 2 < NC)
            mm_load(sb + ((ck + 2) % 3) * STAGE_MM, Ah, Al, Bh, Bl,
                    m0, n0, K, (ck + 2) << 5, tid);
        cp_commit();
        cp_wait2();
        __syncthreads();

        const uint32_t st = sb + (ck % 3) * STAGE_MM;
        #pragma unroll
        for (int ks = 0; ks < 2; ks++) {
            const int k0 = ks * 16;
            uint32_t ah[2][4], al[2][4], bh[8][2], bl[8][2];
            #pragma unroll
            for (int mi = 0; mi < 2; mi++) {
                uint32_t ad = st + (a_row + mi * 16) * PAD_ROW + (k0 + a_kof) * 2;
                LDSM4(ah[mi][0], ah[mi][1], ah[mi][2], ah[mi][3], ad + S_AH);
                LDSM4(al[mi][0], al[mi][1], al[mi][2], al[mi][3], ad + S_AL);
            }
            #pragma unroll
            for (int nj = 0; nj < 8; nj += 2) {
                uint32_t bd = st + (b_row + nj * 8) * PAD_ROW + (k0 + b_kof) * 2;
                LDSM4(bh[nj][0], bh[nj][1], bh[nj+1][0], bh[nj+1][1], bd + S_BH);
                LDSM4(bl[nj][0], bl[nj][1], bl[nj+1][0], bl[nj+1][1], bd + S_BL);
            }
            #pragma unroll
            for (int mi = 0; mi < 2; mi++)
                #pragma unroll
                for (int ni = 0; ni < 8; ni++)
                    MMA16816(c[mi][ni], ah[mi], bh[ni]);
            #pragma unroll
            for (int mi = 0; mi < 2; mi++)
                #pragma unroll
                for (int ni = 0; ni < 8; ni++)
                    MMA16816(c[mi][ni], ah[mi], bl[ni]);
            #pragma unroll
            for (int mi = 0; mi < 2; mi++)
                #pragma unroll
                for (int ni = 0; ni < 8; ni++)
                    MMA16816(c[mi][ni], al[mi], bh[ni]);
        }
        __syncthreads();
    }

    #pragma unroll
    for (int mi = 0; mi < 2; mi++) {
        const int mr = m0 + wm + mi * 16 + (lane >> 2);
        #pragma unroll
        for (int half = 0; half < 2; half++) {
            const int m = mr + half * 8;
            #pragma unroll
            for (int ni = 0; ni < 8; ni++) {
                const int n = n0 + wn + ni * 8 + 2 * (lane & 3);
                float v0 = c[mi][ni][half * 2 + 0];
                float v1 = c[mi][ni][half * 2 + 1];
                if (EPI & EPI_BIAS) { v0 += bias[n]; v1 += bias[n + 1]; }
                if (EPI & EPI_RES) {
                    float2 r2 = *(const float2*)(res + (size_t)m * N + n);
                    v0 += r2.x; v1 += r2.y;
                }
                if (EPI & EPI_GELU) {
                    v0 = 0.5f * v0 * (1.f + erff(v0 * 0.70710678118654752f));
                    v1 = 0.5f * v1 * (1.f + erff(v1 * 0.70710678118654752f));
                }
                if (EPI & EPI_SPLIT) {
                    uint32_t hi, lo;
                    split2(v0, v1, hi, lo);
                    *(uint32_t*)(Ch + (size_t)m * N + n) = hi;
                    *(uint32_t*)(Cl + (size_t)m * N + n) = lo;
                } else {
                    *(float2*)(C + (size_t)m * N + n) = make_float2(v0, v1);
                }
            }
        }
    }
}

// ---------------- fp32 -> bf16 hi/lo conversion (weights) ------------------
__global__ void __launch_bounds__(256) cvt_kernel(
    const float* __restrict__ in, __nv_bfloat16* __restrict__ hi,
    __nv_bfloat16* __restrict__ lo, int n4)
{
    int i = blockIdx.x * 256 + threadIdx.x;
    if (i >= n4) return;
    float4 x = ((const float4*)in)[i];
    uint32_t h0, l0, h1, l1;
    split2(x.x, x.y, h0, l0);
    split2(x.z, x.w, h1, l1);
    ((uint32_t*)hi)[2*i]   = h0;
    ((uint32_t*)hi)[2*i+1] = h1;
    ((uint32_t*)lo)[2*i]   = l0;
    ((uint32_t*)lo)[2*i+1] = l1;
}

// ---------------- pack Wq|Wk|Wv -> padded [256 x 64] bf16 hi/lo ------------
__global__ void __launch_bounds__(256) pack_qkv_kernel(
    const float* __restrict__ Wq, const float* __restrict__ Wk,
    const float* __restrict__ Wv,
    __nv_bfloat16* __restrict__ wh, __nv_bfloat16* __restrict__ wl)
{
    int i = blockIdx.x * 256 + threadIdx.x;   // 0..16383
    int row = i >> 6, col = i & 63;
    float v = 0.f;
    if (row < 64)       v = Wq[row * 64 + col];
    else if (row < 128) v = Wk[(row - 64) * 64 + col];
    else if (row < 192) v = Wv[(row - 128) * 64 + col];
    __nv_bfloat16 h = __float2bfloat16(v);
    wh[i] = h;
    wl[i] = __float2bfloat16(v - __bfloat162float(h));
}

// ================= HMMA flash attention (causal, online softmax) ===========
// reads bf16 hi/lo packed qkv rows of stride 256: [q|k|v|pad] x 64
// Block: 128 q-rows, 8 warps (warp = 16 q-rows x 64 k-cols), K/V tiles of 64
// tokens double-buffered. S and PV via 3-pass hi/lo HMMA, fp32 accum.
#define AT_STRIDE 144                 // bytes per smem row (128B data + 16B pad)
#define AT_Q_H 0
#define AT_Q_L (128*AT_STRIDE)        // 18432
#define AT_ST(s) (2*128*AT_STRIDE + (s)*4*64*AT_STRIDE)
#define AT_KH 0
#define AT_KL (64*AT_STRIDE)
#define AT_VH (2*64*AT_STRIDE)
#define AT_VL (3*64*AT_STRIDE)
#define ATTN_SMEM (2*128*AT_STRIDE + 2*4*64*AT_STRIDE)   // 110592

__device__ __forceinline__ void at_load_kv(
    uint32_t st, const __nv_bfloat16* __restrict__ qkvh,
    const __nv_bfloat16* __restrict__ qkvl, int b, int h, int k0, int tid)
{
    #pragma unroll
    for (int j = 0; j < 2; j++) {
        int idx = tid + j * 256;          // 0..511
        int row = idx >> 3, seg = idx & 7;
        size_t src = ((size_t)(b * T_ + k0 + row) * H_ + h) * 256 + seg * 8;
        uint32_t dst = st + row * AT_STRIDE + seg * 16;
        cp16(dst + AT_KH, qkvh + src + 64);
        cp16(dst + AT_KL, qkvl + src + 64);
        cp16(dst + AT_VH, qkvh + src + 128);
        cp16(dst + AT_VL, qkvl + src + 128);
    }
}

__global__ void __launch_bounds__(256) attn_kernel(
    const __nv_bfloat16* __restrict__ qkvh,
    const __nv_bfloat16* __restrict__ qkvl,
    __nv_bfloat16* __restrict__ oh, __nv_bfloat16* __restrict__ ol)
{
    extern __shared__ char smraw[];
    const uint32_t sb = smem_u32(smraw);
    const int tid  = threadIdx.x;
    const int lane = tid & 31;
    const int wid  = tid >> 5;           // 0..7
    const int wq   = wid * 16;           // warp q-row offset in block
    const int q0   = blockIdx.x * 128;
    const int bh   = blockIdx.y;
    const int b    = bh / H_, h = bh % H_;
    const int NT   = (q0 >> 6) + 2;      // K tiles to visit

    // stage Q tile [128 x 64] hi/lo
    #pragma unroll
    for (int j = 0; j < 4; j++) {
        int idx = tid + j * 256;         // 0..1023
        int row = idx >> 3, seg = idx & 7;
        size_t src = ((size_t)(b * T_ + q0 + row) * H_ + h) * 256 + seg * 8;
        uint32_t dst = sb + row * AT_STRIDE + seg * 16;
        cp16(dst + AT_Q_H, qkvh + src);
        cp16(dst + AT_Q_L, qkvl + src);
    }
    at_load_kv(sb + AT_ST(0), qkvh, qkvl, b, h, 0, tid);
    cp_commit();

    uint32_t qh[4][4], ql[4][4];
    float o[8][4];
    #pragma unroll
    for (int nj = 0; nj < 8; nj++)
        #pragma unroll
        for (int r = 0; r < 4; r++) o[nj][r] = 0.f;
    float m0 = -1e30f, m1 = -1e30f, l0 = 0.f, l1 = 0.f;

    const int qr0 = q0 + wq + (lane >> 2);
    const int qr1 = qr0 + 8;

    for (int kt = 0; kt < NT; kt++) {
        if (kt + 1 < NT)
            at_load_kv(sb + AT_ST((kt + 1) & 1), qkvh, qkvl, b, h,
                       (kt + 1) * 64, tid);
        cp_commit();
        cp_wait1();
        __syncthreads();

        if (kt == 0) {
            #pragma unroll
            for (int k4 = 0; k4 < 4; k4++) {
                uint32_t ad = sb + (wq + (lane & 15)) * AT_STRIDE
                              + (k4 * 16 + (lane >> 4) * 8) * 2;
                LDSM4(qh[k4][0], qh[k4][1], qh[k4][2], qh[k4][3], ad + AT_Q_H);
                LDSM4(ql[k4][0], ql[k4][1], ql[k4][2], ql[k4][3], ad + AT_Q_L);
            }
        }

        const int k0 = kt * 64;
        if (k0 <= q0 + wq + 15) {
            const uint32_t st = sb + AT_ST(kt & 1);

            // ---- S = Q K^T (3-pass hi/lo) ----
            float s[8][4];
            #pragma unroll
            for (int nj = 0; nj < 8; nj++)
                #pragma unroll
                for (int r = 0; r < 4; r++) s[nj][r] = 0.f;

            #pragma unroll
            for (int k4 = 0; k4 < 4; k4++) {
                uint32_t khf[8][2], klf[8][2];
                #pragma unroll
                for (int nj = 0; nj < 8; nj += 2) {
                    int row = nj * 8 + (lane & 7) + ((lane >> 4) & 1) * 8;
                    uint32_t ad = st + row * AT_STRIDE
                                  + (k4 * 16 + ((lane >> 3) & 1) * 8) * 2;
                    LDSM4(khf[nj][0], khf[nj][1], khf[nj+1][0], khf[nj+1][1],
                          ad + AT_KH);
                    LDSM4(klf[nj][0], klf[nj][1], klf[nj+1][0], klf[nj+1][1],
                          ad + AT_KL);
                }
                #pragma unroll
                for (int nj = 0; nj < 8; nj++) MMA16816(s[nj], qh[k4], khf[nj]);
                #pragma unroll
                for (int nj = 0; nj < 8; nj++) MMA16816(s[nj], qh[k4], klf[nj]);
                #pragma unroll
                for (int nj = 0; nj < 8; nj++) MMA16816(s[nj], ql[k4], khf[nj]);
            }

            // ---- online softmax on fragments ----
            const bool msk = (k0 + 63 > q0 + wq);
            float vm0 = -1e30f, vm1 = -1e30f;
            #pragma unroll
            for (int nj = 0; nj < 8; nj++) {
                float v0 = s[nj][0] * 0.125f, v1 = s[nj][1] * 0.125f;
                float v2 = s[nj][2] * 0.125f, v3 = s[nj][3] * 0.125f;
                if (msk) {
                    int gc = k0 + nj * 8 + 2 * (lane & 3);
                    if (gc > qr0)     v0 = -1e30f;
                    if (gc + 1 > qr0) v1 = -1e30f;
                    if (gc > qr1)     v2 = -1e30f;
                    if (gc + 1 > qr1) v3 = -1e30f;
                }
                s[nj][0] = v0; s[nj][1] = v1; s[nj][2] = v2; s[nj][3] = v3;
                vm0 = fmaxf(vm0, fmaxf(v0, v1));
                vm1 = fmaxf(vm1, fmaxf(v2, v3));
            }
            vm0 = fmaxf(vm0, __shfl_xor_sync(0xffffffffu, vm0, 1));
            vm0 = fmaxf(vm0, __shfl_xor_sync(0xffffffffu, vm0, 2));
            vm1 = fmaxf(vm1, __shfl_xor_sync(0xffffffffu, vm1, 1));
            vm1 = fmaxf(vm1, __shfl_xor_sync(0xffffffffu, vm1, 2));
            float mn0 = fmaxf(m0, vm0), mn1 = fmaxf(m1, vm1);
            float a0 = __expf(m0 - mn0), a1 = __expf(m1 - mn1);
            float s0 = 0.f, s1 = 0.f;
            #pragma unroll
            for (int nj = 0; nj < 8; nj++) {
                s[nj][0] = __expf(s[nj][0] - mn0); s0 += s[nj][0];
                s[nj][1] = __expf(s[nj][1] - mn0); s0 += s[nj][1];
                s[nj][2] = __expf(s[nj][2] - mn1); s1 += s[nj][2];
                s[nj][3] = __expf(s[nj][3] - mn1); s1 += s[nj][3];
            }
            s0 += __shfl_xor_sync(0xffffffffu, s0, 1);
            s0 += __shfl_xor_sync(0xffffffffu, s0, 2);
            s1 += __shfl_xor_sync(0xffffffffu, s1, 1);
            s1 += __shfl_xor_sync(0xffffffffu, s1, 2);
            l0 = l0 * a0 + s0; l1 = l1 * a1 + s1;
            m0 = mn0; m1 = mn1;
            #pragma unroll
            for (int nj = 0; nj < 8; nj++) {
                o[nj][0] *= a0; o[nj][1] *= a0;
                o[nj][2] *= a1; o[nj][3] *= a1;
            }

            // ---- pack P into bf16 hi/lo A-frags ----
            uint32_t ph[4][4], pl[4][4];
            #pragma unroll
            for (int k4 = 0; k4 < 4; k4++) {
                split2(s[2*k4][0],   s[2*k4][1],   ph[k4][0], pl[k4][0]);
                split2(s[2*k4][2],   s[2*k4][3],   ph[k4][1], pl[k4][1]);
                split2(s[2*k4+1][0], s[2*k4+1][1], ph[k4][2], pl[k4][2]);
                split2(s[2*k4+1][2], s[2*k4+1][3], ph[k4][3], pl[k4][3]);
            }

            // ---- O += P V (3-pass hi/lo), V via ldmatrix.trans ----
            #pragma unroll
            for (int k4 = 0; k4 < 4; k4++) {
                uint32_t vhf[8][2], vlf[8][2];
                #pragma unroll
                for (int nj = 0; nj < 8; nj += 2) {
                    int krow = k4 * 16 + ((lane >> 3) & 1) * 8 + (lane & 7);
                    int ncol = nj * 8 + (lane >> 4) * 8;
                    uint32_t ad = st + krow * AT_STRIDE + ncol * 2;
                    LDSM4T(vhf[nj][0], vhf[nj][1], vhf[nj+1][0], vhf[nj+1][1],
                           ad + AT_VH);
                    LDSM4T(vlf[nj][0], vlf[nj][1], vlf[nj+1][0], vlf[nj+1][1],
                           ad + AT_VL);
                }
                #pragma unroll
                for (int nj = 0; nj < 8; nj++) MMA16816(o[nj], ph[k4], vhf[nj]);
                #pragma unroll
                for (int nj = 0; nj < 8; nj++) MMA16816(o[nj], ph[k4], vlf[nj]);
                #pragma unroll
                for (int nj = 0; nj < 8; nj++) MMA16816(o[nj], pl[k4], vhf[nj]);
            }
        }
        __syncthreads();
    }

    // ---- write O as bf16 hi/lo split (feeds Wo GEMM) ----
    const float inv0 = 1.0f / l0, inv1 = 1.0f / l1;
    const size_t tok0 = (size_t)(b * T_ + q0 + wq + (lane >> 2));
    #pragma unroll
    for (int nj = 0; nj < 8; nj++) {
        const int col = h * 64 + nj * 8 + 2 * (lane & 3);
        uint32_t hi, lo;
        split2(o[nj][0] * inv0, o[nj][1] * inv0, hi, lo);
        *(uint32_t*)(oh + tok0 * E_ + col) = hi;
        *(uint32_t*)(ol + tok0 * E_ + col) = lo;
        split2(o[nj][2] * inv1, o[nj][3] * inv1, hi, lo);
        *(uint32_t*)(oh + (tok0 + 8) * E_ + col) = hi;
        *(uint32_t*)(ol + (tok0 + 8) * E_ + col) = lo;
    }
}

// ---------------- layernorm (+ fused bf16 hi/lo split output) --------------
__global__ void __launch_bounds__(256) ln_kernel(
    const float* __restrict__ in, const float* __restrict__ gg,
    const float* __restrict__ bb, float* __restrict__ out,
    __nv_bfloat16* __restrict__ oh, __nv_bfloat16* __restrict__ ol)
{
    __shared__ float red[8];
    const int row = blockIdx.x;
    const int tid = threadIdx.x;
    float4 vx = ((const float4*)(in + (size_t)row * E_))[tid];
    float s = vx.x + vx.y + vx.z + vx.w;
    #pragma unroll
    for (int o = 16; o; o >>= 1) s += __shfl_xor_sync(0xffffffffu, s, o);
    if ((tid & 31) == 0) red[tid >> 5] = s;
    __syncthreads();
    float mean = (red[0]+red[1]+red[2]+red[3]+red[4]+red[5]+red[6]+red[7]) * (1.f/E_);
    __syncthreads();
    float dx = vx.x - mean, dy = vx.y - mean, dz = vx.z - mean, dw = vx.w - mean;
    float s2 = dx*dx + dy*dy + dz*dz + dw*dw;
    #pragma unroll
    for (int o = 16; o; o >>= 1) s2 += __shfl_xor_sync(0xffffffffu, s2, o);
    if ((tid & 31) == 0) red[tid >> 5] = s2;
    __syncthreads();
    float var = (red[0]+red[1]+red[2]+red[3]+red[4]+red[5]+red[6]+red[7]) * (1.f/E_);
    float rstd = rsqrtf(var + 1e-5f);
    float4 g4 = ((const float4*)gg)[tid];
    float4 b4 = ((const float4*)bb)[tid];
    float4 o4 = make_float4(dx*rstd*g4.x + b4.x, dy*rstd*g4.y + b4.y,
                            dz*rstd*g4.z + b4.z, dw*rstd*g4.w + b4.w);
    ((float4*)(out + (size_t)row * E_))[tid] = o4;
    uint32_t h0, l0, h1, l1;
    split2(o4.x, o4.y, h0, l0);
    split2(o4.z, o4.w, h1, l1);
    uint32_t* ph = (uint32_t*)(oh + (size_t)row * E_);
    uint32_t* pl = (uint32_t*)(ol + (size_t)row * E_);
    ph[tid*2]   = h0; ph[tid*2+1] = h1;
    pl[tid*2]   = l0; pl[tid*2+1] = l1;
}

// ---------------- token+pos embedding (+ split) -----------------------------
__global__ void __launch_bounds__(256) embed_kernel(
    const int* __restrict__ idx, const float* __restrict__ tok,
    const float* __restrict__ pos, float* __restrict__ out,
    __nv_bfloat16* __restrict__ oh, __nv_bfloat16* __restrict__ ol)
{
    int gid = blockIdx.x * 256 + threadIdx.x;
    int e4 = gid & (E_/4 - 1);
    int bt = gid >> 8;
    int t  = bt & (T_ - 1);
    int token = idx[bt];
    float4 a = ((const float4*)(tok + (size_t)token * E_))[e4];
    float4 p = ((const float4*)(pos + (size_t)t * E_))[e4];
    float4 v = make_float4(a.x+p.x, a.y+p.y, a.z+p.z, a.w+p.w);
    ((float4*)out)[gid] = v;
    uint32_t h0, l0, h1, l1;
    split2(v.x, v.y, h0, l0);
    split2(v.z, v.w, h1, l1);
    ((uint32_t*)oh)[2*gid]   = h0;
    ((uint32_t*)oh)[2*gid+1] = h1;
    ((uint32_t*)ol)[2*gid]   = l0;
    ((uint32_t*)ol)[2*gid+1] = l1;
}

// ---------------- loss -----------------------------------------------------
__global__ void __launch_bounds__(256) loss_tok_kernel(
    const float* __restrict__ logits, const int* __restrict__ targets,
    float* __restrict__ tokloss)
{
    __shared__ float red[8];
    const int row = blockIdx.x;
    const int tid = threadIdx.x;
    const float* lg = logits + (size_t)row * V_;
    float mx = -1e30f;
    for (int i = tid; i < V_; i += 256) mx = fmaxf(mx, lg[i]);
    #pragma unroll
    for (int o = 16; o; o >>= 1) mx = fmaxf(mx, __shfl_xor_sync(0xffffffffu, mx, o));
    if ((tid & 31) == 0) red[tid >> 5] = mx;
    __syncthreads();
    mx = fmaxf(fmaxf(fmaxf(red[0], red[1]), fmaxf(red[2], red[3])),
               fmaxf(fmaxf(red[4], red[5]), fmaxf(red[6], red[7])));
    __syncthreads();
    float s = 0.f;
    for (int i = tid; i < V_; i += 256) s += __expf(lg[i] - mx);
    #pragma unroll
    for (int o = 16; o; o >>= 1) s += __shfl_xor_sync(0xffffffffu, s, o);
    if ((tid & 31) == 0) red[tid >> 5] = s;
    __syncthreads();
    if (tid == 0) {
        float tot = red[0]+red[1]+red[2]+red[3]+red[4]+red[5]+red[6]+red[7];
        tokloss[row] = -(lg[targets[row]] - mx - logf(tot));
    }
}

__global__ void __launch_bounds__(256) loss_reduce_kernel(
    const float* __restrict__ tokloss, float* __restrict__ outp)
{
    __shared__ float red[8];
    const int tid = threadIdx.x;
    float s = 0.f;
    for (int i = tid; i < BT_; i += 256) s += tokloss[i];
    #pragma unroll
    for (int o = 16; o; o >>= 1) s += __shfl_xor_sync(0xffffffffu, s, o);
    if ((tid & 31) == 0) red[tid >> 5] = s;
    __syncthreads();
    if (tid == 0) {
        float tot = red[0]+red[1]+red[2]+red[3]+red[4]+red[5]+red[6]+red[7];
        outp[0] = tot / (float)BT_;
    }
}

// ---------------- host driver ----------------------------------------------
extern "C" void kernel_launch(void* const* d_in, const int* in_sizes, int n_in,
                              void* d_out, int out_size)
{
    const int*   idx  = (const int*)  d_in[0];
    const int*   tgt  = (const int*)  d_in[1];
    const float* tok  = (const float*)d_in[2];
    const float* pos  = (const float*)d_in[3];
    const float* Wq   = (const float*)d_in[4];
    const float* Wk   = (const float*)d_in[5];
    const float* Wv   = (const float*)d_in[6];
    const float* Wo   = (const float*)d_in[7];
    const float* bo   = (const float*)d_in[8];
    const float* ln1g = (const float*)d_in[9];
    const float* ln1b = (const float*)d_in[10];
    const float* W1   = (const float*)d_in[11];
    const float* b1   = (const float*)d_in[12];
    const float* W2   = (const float*)d_in[13];
    const float* b2   = (const float*)d_in[14];
    const float* ln2g = (const float*)d_in[15];
    const float* ln2b = (const float*)d_in[16];
    const float* lnfg = (const float*)d_in[17];
    const float* lnfb = (const float*)d_in[18];
    const float* lmw  = (const float*)d_in[19];
    const float* lmb  = (const float*)d_in[20];

    float *x, *y, *lscratch, *tokloss;
    __nv_bfloat16 *qkvh, *qkvl, *xh, *xl, *hh, *hl, *wh, *wl, *wqh, *wql;
    cudaGetSymbolAddress((void**)&x,        g_x);
    cudaGetSymbolAddress((void**)&y,        g_y);
    cudaGetSymbolAddress((void**)&lscratch, g_logits);
    cudaGetSymbolAddress((void**)&tokloss,  g_tokloss);
    cudaGetSymbolAddress((void**)&qkvh,     g_qkvh);
    cudaGetSymbolAddress((void**)&qkvl,     g_qkvl);
    cudaGetSymbolAddress((void**)&xh,       g_xh);
    cudaGetSymbolAddress((void**)&xl,       g_xl);
    cudaGetSymbolAddress((void**)&hh,       g_hh);
    cudaGetSymbolAddress((void**)&hl,       g_hl);
    cudaGetSymbolAddress((void**)&wh,       g_wh);
    cudaGetSymbolAddress((void**)&wl,       g_wl);
    cudaGetSymbolAddress((void**)&wqh,      g_wqh);
    cudaGetSymbolAddress((void**)&wql,      g_wql);

    const size_t LOG_N = (size_t)BT_ * V_;
    float* logits_ptr = ((size_t)out_size >= LOG_N) ? (float*)d_out : lscratch;
    float* loss_ptr = nullptr;
    if ((size_t)out_size >= LOG_N + 1) loss_ptr = (float*)d_out + LOG_N;
    else if ((size_t)out_size < LOG_N) loss_ptr = (float*)d_out;

    cudaFuncSetAttribute(attn_kernel, cudaFuncAttributeMaxDynamicSharedMemorySize,
                         ATTN_SMEM);
    cudaFuncSetAttribute(gemm_mm<EPI_SPLIT>,
                         cudaFuncAttributeMaxDynamicSharedMemorySize, SMEM_MM);
    cudaFuncSetAttribute(gemm_mm<EPI_BIAS|EPI_RES>,
                         cudaFuncAttributeMaxDynamicSharedMemorySize, SMEM_MM);
    cudaFuncSetAttribute(gemm_mm<EPI_BIAS|EPI_GELU|EPI_SPLIT>,
                         cudaFuncAttributeMaxDynamicSharedMemorySize, SMEM_MM);
    cudaFuncSetAttribute(gemm_mm<EPI_BIAS>,
                         cudaFuncAttributeMaxDynamicSharedMemorySize, SMEM_MM);

    embed_kernel<<<BT_*(E_/4)/256, 256>>>(idx, tok, pos, x, xh, xl);

    for (int l = 0; l < NL_; l++) {
        // QKV via HMMA, epilogue writes bf16 hi/lo split directly
        pack_qkv_kernel<<<64, 256>>>(Wq + (size_t)l*DH_*DH_,
                                     Wk + (size_t)l*DH_*DH_,
                                     Wv + (size_t)l*DH_*DH_, wqh, wql);
        gemm_mm<EPI_SPLIT><<<dim3(MQKV_/256, 2), 512, SMEM_MM>>>(
            xh, xl, wqh, wql, nullptr, nullptr, nullptr, qkvh, qkvl,
            MQKV_, 256, 64);

        // HMMA flash attention, writes bf16 split into xh/xl
        attn_kernel<<<dim3(T_/128, B_*H_), 256, ATTN_SMEM>>>(qkvh, qkvl, xh, xl);

        // out-proj: y = att @ Wo^T + bo + x
        cvt_kernel<<<(E_*E_/4)/256, 256>>>(Wo + (size_t)l*E_*E_, wh, wl, E_*E_/4);
        gemm_mm<EPI_BIAS|EPI_RES><<<dim3(BT_/256, E_/128), 512, SMEM_MM>>>(
            xh, xl, wh, wl, bo + (size_t)l*E_, x, y, nullptr, nullptr,
            BT_, E_, E_);
        ln_kernel<<<BT_, 256>>>(y, ln1g + (size_t)l*E_, ln1b + (size_t)l*E_,
                                x, xh, xl);

        // FF1: h = gelu(x @ W1^T + b1), written directly as bf16 hi/lo
        cvt_kernel<<<(FF_*E_/4)/256, 256>>>(W1 + (size_t)l*FF_*E_, wh, wl, FF_*E_/4);
        gemm_mm<EPI_BIAS|EPI_GELU|EPI_SPLIT><<<dim3(BT_/256, FF_/128), 512, SMEM_MM>>>(
            xh, xl, wh, wl, b1 + (size_t)l*FF_, nullptr, nullptr, hh, hl,
            BT_, FF_, E_);

        // FF2: y = h @ W2^T + b2 + x
        cvt_kernel<<<(E_*FF_/4)/256, 256>>>(W2 + (size_t)l*E_*FF_, wh, wl, E_*FF_/4);
        gemm_mm<EPI_BIAS|EPI_RES><<<dim3(BT_/256, E_/128), 512, SMEM_MM>>>(
            hh, hl, wh, wl, b2 + (size_t)l*E_, x, y, nullptr, nullptr,
            BT_, E_, FF_);
        ln_kernel<<<BT_, 256>>>(y, ln2g + (size_t)l*E_, ln2b + (size_t)l*E_,
                                x, xh, xl);
    }

    ln_kernel<<<BT_, 256>>>(x, lnfg, lnfb, y, xh, xl);

    // LM head
    cvt_kernel<<<((size_t)V_*E_/4)/256, 256>>>(lmw, wh, wl, V_*E_/4);
    gemm_mm<EPI_BIAS><<<dim3(BT_/256, V_/128), 512, SMEM_MM>>>(
        xh, xl, wh, wl, lmb, nullptr, logits_ptr, nullptr, nullptr,
        BT_, V_, E_);

    if (loss_ptr) {
        loss_tok_kernel<<<BT_, 256>>>(logits_ptr, tgt, tokloss);
        loss_reduce_kernel<<<1, 256>>>(tokloss, loss_ptr);
    }
}